// round 1
// baseline (speedup 1.0000x reference)
#include <cuda_runtime.h>

// ---------------- problem constants ----------------
#define B_  8
#define S_  1024
#define D_  1024
#define H_  16
#define DH_ 64
#define R_  256
#define NC_ 64
#define NE_ 64
#define KC_ 16
#define KE_ 8

// ---------------- scratch (device globals; no allocation allowed) ----------
__device__ float g_Wall[256 * D_];                 // 1 MB  concat of 4 routers
__device__ float g_logits[B_ * S_ * 256];          // 8 MB
__device__ float g_tw[4 * B_ * 16];                // router top-k weights
__device__ int   g_ti[4 * B_ * 16];                // router top-k indices
__device__ float g_sharedc[B_ * D_ * R_];          // 8 MB   [b][d][r]
__device__ float g_h[B_ * S_ * R_];                // 8 MB   [b][s][r]
__device__ float g_eAll[B_ * R_ * 3 * D_];         // 24 MB  [b][r][3D] (Q|K|V)
__device__ float g_qkv[B_ * S_ * 3 * D_];          // 96 MB  [b][s][3D]
__device__ float g_aout[B_ * S_ * D_];             // 32 MB  attention output

// ---------------- generic tiled SGEMM ----------------
// C[M,N] = A[M,K] @ op(B).  TB=0: B is [K,N].  TB=1: B is [N,K] (C=A@B^T).
// 128x128 block tile, BK=8, 256 threads, 8x8 microtile, double-buffered smem.
template <int TB>
__global__ __launch_bounds__(256, 2) void sgemm_kernel(
    const float* __restrict__ A, const float* __restrict__ Bm,
    float* __restrict__ C, int M, int N, int K,
    long long sA, long long sB, long long sC)
{
    __shared__ float As[2][8][128];
    __shared__ float Bs[2][8][128];

    const float* Ab = A  + (long long)blockIdx.z * sA;
    const float* Bb = Bm + (long long)blockIdx.z * sB;
    float*       Cb = C  + (long long)blockIdx.z * sC;

    const int tid = threadIdx.x;
    const int m0 = blockIdx.x * 128, n0 = blockIdx.y * 128;
    const int tx = tid & 15, ty = tid >> 4;

    const int lr = tid >> 1;            // 0..127
    const int lk = (tid & 1) << 2;      // 0 or 4
    const int bk = tid >> 5;            // 0..7  (TB=0)
    const int bn = (tid & 31) << 2;     // 0..124 (TB=0)

    const float* Ap   = Ab + (long long)(m0 + lr) * K + lk;
    const float* Bp_t = Bb + (long long)(n0 + lr) * K + lk;       // TB=1
    const float* Bp_n = Bb + (long long)bk * N + n0 + bn;         // TB=0

    float4 ar, br;
    ar = *(const float4*)(Ap);
    br = TB ? *(const float4*)(Bp_t) : *(const float4*)(Bp_n);
    As[0][lk + 0][lr] = ar.x; As[0][lk + 1][lr] = ar.y;
    As[0][lk + 2][lr] = ar.z; As[0][lk + 3][lr] = ar.w;
    if (TB) {
        Bs[0][lk + 0][lr] = br.x; Bs[0][lk + 1][lr] = br.y;
        Bs[0][lk + 2][lr] = br.z; Bs[0][lk + 3][lr] = br.w;
    } else {
        *(float4*)&Bs[0][bk][bn] = br;
    }
    __syncthreads();

    float acc[8][8];
#pragma unroll
    for (int i = 0; i < 8; i++)
#pragma unroll
        for (int j = 0; j < 8; j++) acc[i][j] = 0.f;

    int buf = 0;
    for (int k0 = 0; k0 < K; k0 += 8) {
        const int kn = k0 + 8;
        if (kn < K) {
            ar = *(const float4*)(Ap + kn);
            br = TB ? *(const float4*)(Bp_t + kn)
                    : *(const float4*)(Bp_n + (long long)kn * N);
        }
#pragma unroll
        for (int kk = 0; kk < 8; ++kk) {
            float4 a0 = *(const float4*)&As[buf][kk][ty * 8];
            float4 a1 = *(const float4*)&As[buf][kk][ty * 8 + 4];
            float4 b0 = *(const float4*)&Bs[buf][kk][tx * 8];
            float4 b1 = *(const float4*)&Bs[buf][kk][tx * 8 + 4];
            float av[8] = {a0.x, a0.y, a0.z, a0.w, a1.x, a1.y, a1.z, a1.w};
            float bv[8] = {b0.x, b0.y, b0.z, b0.w, b1.x, b1.y, b1.z, b1.w};
#pragma unroll
            for (int i = 0; i < 8; i++)
#pragma unroll
                for (int j = 0; j < 8; j++)
                    acc[i][j] = fmaf(av[i], bv[j], acc[i][j]);
        }
        if (kn < K) {
            const int nb = buf ^ 1;
            As[nb][lk + 0][lr] = ar.x; As[nb][lk + 1][lr] = ar.y;
            As[nb][lk + 2][lr] = ar.z; As[nb][lk + 3][lr] = ar.w;
            if (TB) {
                Bs[nb][lk + 0][lr] = br.x; Bs[nb][lk + 1][lr] = br.y;
                Bs[nb][lk + 2][lr] = br.z; Bs[nb][lk + 3][lr] = br.w;
            } else {
                *(float4*)&Bs[nb][bk][bn] = br;
            }
            buf = nb;
            __syncthreads();
        }
    }

#pragma unroll
    for (int i = 0; i < 8; i++) {
        const long long row = (long long)(m0 + ty * 8 + i);
        float4 c0 = {acc[i][0], acc[i][1], acc[i][2], acc[i][3]};
        float4 c1 = {acc[i][4], acc[i][5], acc[i][6], acc[i][7]};
        *(float4*)&Cb[row * N + n0 + tx * 8]     = c0;
        *(float4*)&Cb[row * N + n0 + tx * 8 + 4] = c1;
    }
}

// ---------------- concat router weights into [256, D] ----------------
__global__ void concat_kernel(const float* __restrict__ a, const float* __restrict__ b,
                              const float* __restrict__ c, const float* __restrict__ d)
{
    int i = blockIdx.x * 256 + threadIdx.x;           // < 262144
    int rt = i >> 16, rem = i & 65535;
    const float* src = (rt == 0) ? a : (rt == 1) ? b : (rt == 2) ? c : d;
    g_Wall[i] = src[rem];
}

// ---------------- router: softmax over n, importance-agg, top-k --------
// grid (4 routers, 8 batches), 256 threads. Deterministic (no atomics).
__global__ void router_kernel(const float* __restrict__ importance)
{
    const int rt = blockIdx.x, b = blockIdx.y;
    const int k = (rt == 0) ? KC_ : KE_;
    __shared__ float wpart[8][64];
    __shared__ float w[64];
    const int tid = threadIdx.x, warp = tid >> 5, lane = tid & 31;

    float acc0 = 0.f, acc1 = 0.f;
    for (int s = warp; s < S_; s += 8) {
        const float* lp = g_logits + ((long long)(b * S_ + s)) * 256 + rt * 64;
        float v0 = lp[lane], v1 = lp[lane + 32];
        float mx = fmaxf(v0, v1);
#pragma unroll
        for (int off = 16; off; off >>= 1) mx = fmaxf(mx, __shfl_xor_sync(~0u, mx, off));
        float e0 = __expf(v0 - mx), e1 = __expf(v1 - mx);
        float sm = e0 + e1;
#pragma unroll
        for (int off = 16; off; off >>= 1) sm += __shfl_xor_sync(~0u, sm, off);
        float c = importance[b * S_ + s] / sm;
        acc0 += e0 * c;
        acc1 += e1 * c;
    }
    wpart[warp][lane]      = acc0;
    wpart[warp][lane + 32] = acc1;
    __syncthreads();
    if (tid < 64) {
        float t = 0.f;
#pragma unroll
        for (int wi = 0; wi < 8; wi++) t += wpart[wi][tid];
        w[tid] = t;
    }
    __syncthreads();
    if (tid == 0) {
        float tot = 0.f;
        for (int n = 0; n < 64; n++) tot += w[n];
        const float inv = 1.f / (tot + 1e-8f);
        float tw[16]; int ti[16]; bool used[64];
        for (int n = 0; n < 64; n++) used[n] = false;
        for (int kk = 0; kk < k; kk++) {
            float best = -1e30f; int bi = 0;
            for (int n = 0; n < 64; n++) {
                float v = w[n] * inv;
                if (!used[n] && v > best) { best = v; bi = n; }
            }
            used[bi] = true; tw[kk] = best; ti[kk] = bi;
        }
        float ts = 0.f;
        for (int kk = 0; kk < k; kk++) ts += tw[kk];
        const float inv2 = 1.f / (ts + 1e-8f);
        for (int kk = 0; kk < k; kk++) {
            g_tw[(rt * B_ + b) * 16 + kk] = tw[kk] * inv2;
            g_ti[(rt * B_ + b) * 16 + kk] = ti[kk];
        }
    }
}

// ---------------- mix compress neurons: shared_c[b][d][r] ----------------
__global__ void mix_compress_kernel(const float* __restrict__ cn)
{
    const int b = blockIdx.y;
    __shared__ float cw[KC_]; __shared__ int ci[KC_];
    if (threadIdx.x < KC_) {
        cw[threadIdx.x] = g_tw[(0 * B_ + b) * 16 + threadIdx.x];
        ci[threadIdx.x] = g_ti[(0 * B_ + b) * 16 + threadIdx.x];
    }
    __syncthreads();
    const long long idx4 = blockIdx.x * blockDim.x + threadIdx.x;  // < 65536
    float4 acc = {0.f, 0.f, 0.f, 0.f};
#pragma unroll
    for (int kk = 0; kk < KC_; kk++) {
        const float4 v = *(const float4*)(cn + (long long)ci[kk] * (D_ * R_) + idx4 * 4);
        const float wv = cw[kk];
        acc.x += wv * v.x; acc.y += wv * v.y; acc.z += wv * v.z; acc.w += wv * v.w;
    }
    *(float4*)(g_sharedc + (long long)b * (D_ * R_) + idx4 * 4) = acc;
}

// ---------------- mix expand pool: eAll[b][r][which*D + d] ----------------
__global__ void mix_expand_kernel(const float* __restrict__ pool)
{
    const int which = blockIdx.y;          // 0=Q,1=K,2=V
    const int b = blockIdx.z;
    const int rt = which + 1;
    __shared__ float ew[KE_]; __shared__ int ei[KE_];
    if (threadIdx.x < KE_) {
        ew[threadIdx.x] = g_tw[(rt * B_ + b) * 16 + threadIdx.x];
        ei[threadIdx.x] = g_ti[(rt * B_ + b) * 16 + threadIdx.x];
    }
    __syncthreads();
    const long long idx4 = blockIdx.x * blockDim.x + threadIdx.x;  // < 65536 (R*D/4)
    float4 acc = {0.f, 0.f, 0.f, 0.f};
#pragma unroll
    for (int kk = 0; kk < KE_; kk++) {
        const float4 v = *(const float4*)(pool + (long long)ei[kk] * (R_ * D_) + idx4 * 4);
        const float wv = ew[kk];
        acc.x += wv * v.x; acc.y += wv * v.y; acc.z += wv * v.z; acc.w += wv * v.w;
    }
    const int d4 = (int)(idx4 & 255), r = (int)(idx4 >> 8);
    *(float4*)(g_eAll + (long long)b * (R_ * 3 * D_) + (long long)r * (3 * D_)
               + which * D_ + d4 * 4) = acc;
}

// ---------------- causal flash attention ----------------
// grid (16 q-tiles, 128 bh). 256 thr = 16x16, each thread a 4x4 microtile.
// Tiles 64x64, d=64. smem mini-GEMMs for QK^T and PV, online softmax.
#define FA_PAD 68
__global__ __launch_bounds__(256) void flash_kernel(const float* __restrict__ qkv,
                                                    float* __restrict__ out)
{
    extern __shared__ float sm[];
    float* Qs  = sm;                 // [d][r]  64x68
    float* Ks  = Qs + 64 * FA_PAD;   // [d][j]
    float* Vs  = Ks + 64 * FA_PAD;   // [j][d]
    float* Pts = Vs + 64 * FA_PAD;   // [j][r]

    const int tid = threadIdx.x;
    const int bh = blockIdx.y;
    const int b = bh >> 4, h = bh & 15;
    const int q0 = blockIdx.x * 64;
    const float* base = qkv + (long long)b * S_ * (3 * D_) + h * DH_;

    // Q load (transposed into smem)
    for (int i = tid; i < 64 * 16; i += 256) {
        const int r = i >> 4, d4 = (i & 15) << 2;
        float4 v = *(const float4*)(base + (long long)(q0 + r) * (3 * D_) + d4);
        Qs[(d4 + 0) * FA_PAD + r] = v.x; Qs[(d4 + 1) * FA_PAD + r] = v.y;
        Qs[(d4 + 2) * FA_PAD + r] = v.z; Qs[(d4 + 3) * FA_PAD + r] = v.w;
    }

    const int tx = tid & 15, ty = tid >> 4;
    float m[4], l[4], o[4][4];
#pragma unroll
    for (int i = 0; i < 4; i++) {
        m[i] = -1e30f; l[i] = 0.f;
#pragma unroll
        for (int j = 0; j < 4; j++) o[i][j] = 0.f;
    }
    const float scale = 0.125f;  // 1/sqrt(64)

    for (int k0 = 0; k0 <= q0; k0 += 64) {
        __syncthreads();
        // K (transposed) + V (natural) tile loads
        for (int i = tid; i < 64 * 16; i += 256) {
            const int j = i >> 4, d4 = (i & 15) << 2;
            float4 kv = *(const float4*)(base + D_ + (long long)(k0 + j) * (3 * D_) + d4);
            Ks[(d4 + 0) * FA_PAD + j] = kv.x; Ks[(d4 + 1) * FA_PAD + j] = kv.y;
            Ks[(d4 + 2) * FA_PAD + j] = kv.z; Ks[(d4 + 3) * FA_PAD + j] = kv.w;
            float4 vv = *(const float4*)(base + 2 * D_ + (long long)(k0 + j) * (3 * D_) + d4);
            *(float4*)&Vs[j * FA_PAD + d4] = vv;
        }
        __syncthreads();

        // scores S = Q K^T  (4x4 per thread)
        float s[4][4];
#pragma unroll
        for (int i = 0; i < 4; i++)
#pragma unroll
            for (int j = 0; j < 4; j++) s[i][j] = 0.f;
#pragma unroll
        for (int d = 0; d < 64; ++d) {
            float4 q4 = *(const float4*)&Qs[d * FA_PAD + ty * 4];
            float4 k4 = *(const float4*)&Ks[d * FA_PAD + tx * 4];
            float qv[4] = {q4.x, q4.y, q4.z, q4.w};
            float kv[4] = {k4.x, k4.y, k4.z, k4.w};
#pragma unroll
            for (int i = 0; i < 4; i++)
#pragma unroll
                for (int j = 0; j < 4; j++)
                    s[i][j] = fmaf(qv[i], kv[j], s[i][j]);
        }
        const bool diag = (k0 == q0);
#pragma unroll
        for (int i = 0; i < 4; i++)
#pragma unroll
            for (int j = 0; j < 4; j++) {
                s[i][j] *= scale;
                if (diag && (tx * 4 + j > ty * 4 + i)) s[i][j] = -1e30f;
            }

        // online softmax per row (reduce across the 16 tx lanes)
#pragma unroll
        for (int i = 0; i < 4; i++) {
            float mx = fmaxf(fmaxf(s[i][0], s[i][1]), fmaxf(s[i][2], s[i][3]));
#pragma unroll
            for (int off = 8; off; off >>= 1)
                mx = fmaxf(mx, __shfl_xor_sync(~0u, mx, off));
            const float mn = fmaxf(m[i], mx);
            const float alpha = __expf(m[i] - mn);
            float ls = 0.f;
#pragma unroll
            for (int j = 0; j < 4; j++) {
                float p = __expf(s[i][j] - mn);
                s[i][j] = p; ls += p;
            }
#pragma unroll
            for (int off = 8; off; off >>= 1)
                ls += __shfl_xor_sync(~0u, ls, off);
            l[i] = l[i] * alpha + ls;
            m[i] = mn;
#pragma unroll
            for (int j = 0; j < 4; j++) o[i][j] *= alpha;
            // store P transposed: Pts[j][r]
#pragma unroll
            for (int j = 0; j < 4; j++)
                Pts[(tx * 4 + j) * FA_PAD + ty * 4 + i] = s[i][j];
        }
        __syncthreads();

        // O += P @ V  (4x4 per thread)
#pragma unroll
        for (int j = 0; j < 64; ++j) {
            float4 p4 = *(const float4*)&Pts[j * FA_PAD + ty * 4];
            float4 v4 = *(const float4*)&Vs[j * FA_PAD + tx * 4];
            float pv[4] = {p4.x, p4.y, p4.z, p4.w};
            float vv[4] = {v4.x, v4.y, v4.z, v4.w};
#pragma unroll
            for (int i = 0; i < 4; i++)
#pragma unroll
                for (int jj = 0; jj < 4; jj++)
                    o[i][jj] = fmaf(pv[i], vv[jj], o[i][jj]);
        }
    }

    float* op = out + (long long)b * S_ * D_ + (long long)q0 * D_ + h * DH_;
#pragma unroll
    for (int i = 0; i < 4; i++) {
        const float inv = 1.f / l[i];
        float4 c = {o[i][0] * inv, o[i][1] * inv, o[i][2] * inv, o[i][3] * inv};
        *(float4*)&op[(long long)(ty * 4 + i) * D_ + tx * 4] = c;
    }
}

// ---------------- launch ----------------
extern "C" void kernel_launch(void* const* d_in, const int* in_sizes, int n_in,
                              void* d_out, int out_size)
{
    const float* x    = (const float*)d_in[0];
    const float* imp  = (const float*)d_in[1];
    const float* Wc   = (const float*)d_in[2];
    const float* Wq   = (const float*)d_in[3];
    const float* Wk   = (const float*)d_in[4];
    const float* Wv   = (const float*)d_in[5];
    const float* cn   = (const float*)d_in[6];
    const float* pool = (const float*)d_in[7];
    const float* WO   = (const float*)d_in[8];
    float* out = (float*)d_out;

    float *pWall, *pLog, *pSc, *pH, *pE, *pQKV, *pAO;
    cudaGetSymbolAddress((void**)&pWall, g_Wall);
    cudaGetSymbolAddress((void**)&pLog,  g_logits);
    cudaGetSymbolAddress((void**)&pSc,   g_sharedc);
    cudaGetSymbolAddress((void**)&pH,    g_h);
    cudaGetSymbolAddress((void**)&pE,    g_eAll);
    cudaGetSymbolAddress((void**)&pQKV,  g_qkv);
    cudaGetSymbolAddress((void**)&pAO,   g_aout);

    // 1. concat router weights
    concat_kernel<<<1024, 256>>>(Wc, Wq, Wk, Wv);
    // 2. routing logits: [8192,1024] @ [256,1024]^T -> [8192,256]
    sgemm_kernel<1><<<dim3(64, 2, 1), 256>>>(x, pWall, pLog, 8192, 256, 1024, 0, 0, 0);
    // 3. routers (softmax, importance agg, top-k)
    router_kernel<<<dim3(4, 8), 256>>>(imp);
    // 4. mix compress neurons -> shared_c
    mix_compress_kernel<<<dim3(256, 8), 256>>>(cn);
    // 5. h = x @ shared_c  (batched)
    sgemm_kernel<0><<<dim3(8, 2, 8), 256>>>(x, pSc, pH, 1024, 256, 1024,
        (long long)S_ * D_, (long long)D_ * R_, (long long)S_ * R_);
    // 6. mix expand pool -> eAll (Q|K|V)
    mix_expand_kernel<<<dim3(256, 3, 8), 256>>>(pool);
    // 7. QKV = h @ eAll  (batched)
    sgemm_kernel<0><<<dim3(8, 24, 8), 256>>>(pH, pE, pQKV, 1024, 3 * D_, R_,
        (long long)S_ * R_, (long long)R_ * 3 * D_, (long long)S_ * 3 * D_);
    // 8. causal flash attention
    const size_t fa_smem = 4 * 64 * FA_PAD * sizeof(float);  // ~69.6 KB
    cudaFuncSetAttribute(flash_kernel, cudaFuncAttributeMaxDynamicSharedMemorySize,
                         (int)fa_smem);
    flash_kernel<<<dim3(16, 128), 256, fa_smem>>>(pQKV, pAO);
    // 9. output projection: aout @ W_O^T
    sgemm_kernel<1><<<dim3(64, 8, 1), 256>>>(pAO, WO, out, 8192, 1024, 1024, 0, 0, 0);
}

// round 3
// speedup vs baseline: 1.1919x; 1.1919x over previous
#include <cuda_runtime.h>
#include <cuda_bf16.h>
#include <cstdint>

// ---------------- problem constants ----------------
#define B_  8
#define S_  1024
#define D_  1024
#define H_  16
#define DH_ 64
#define R_  256
#define NC_ 64
#define NE_ 64
#define KC_ 16
#define KE_ 8

// ---------------- scratch (device globals; no allocation allowed) ----------
__device__ float g_Wall[256 * D_];                 // [256][D]   router weights (N-major, K contig)
__device__ float g_logits[B_ * S_ * 256];          // [b*s][256]
__device__ float g_tw[4 * B_ * 16];
__device__ int   g_ti[4 * B_ * 16];
__device__ float g_sharedcT[B_ * R_ * D_];         // [b][r][d]  (transposed!)
__device__ float g_h[B_ * S_ * R_];                // [b][s][r]
__device__ float g_eAllT[B_ * 3 * D_ * R_];        // [b][3D][r] (transposed!)
__device__ float g_qkv[B_ * S_ * 3 * D_];          // [b][s][3D]
__device__ float g_aout[B_ * S_ * D_];             // [b][s][D]

// =======================================================================
// split-bf16 mma.sync GEMM:  C[M,N] = A[M,K] @ B[N,K]^T   (all fp32 gmem)
// 128x128 CTA tile, BK=32, 256 threads (8 warps of 64x32), double buffer.
// =======================================================================
#define GPITCH 40                           // bf16 elems per smem row (80B; 5 coprime 8 -> ldmatrix conflict-free)
#define TILE_BYTES (128 * GPITCH * 2)       // 10240 per sub-tile
#define STAGE_BYTES (4 * TILE_BYTES)        // Ahi|Alo|Bhi|Blo = 40960
#define GEMM_SMEM (2 * STAGE_BYTES)         // 81920

__device__ __forceinline__ uint32_t smem_u32(const void* p) {
    uint32_t a;
    asm("{ .reg .u64 t; cvta.to.shared.u64 t, %1; cvt.u32.u64 %0, t; }"
        : "=r"(a) : "l"(p));
    return a;
}

__device__ __forceinline__ void split2(float x, float y, uint32_t& hi, uint32_t& lo) {
    __nv_bfloat16 hx = __float2bfloat16(x);
    __nv_bfloat16 hy = __float2bfloat16(y);
    __nv_bfloat16 lx = __float2bfloat16(x - __bfloat162float(hx));
    __nv_bfloat16 ly = __float2bfloat16(y - __bfloat162float(hy));
    hi = ((uint32_t)__bfloat16_as_ushort(hy) << 16) | __bfloat16_as_ushort(hx);
    lo = ((uint32_t)__bfloat16_as_ushort(ly) << 16) | __bfloat16_as_ushort(lx);
}

__device__ __forceinline__ void ldm_x4(uint32_t* r, uint32_t addr) {
    asm volatile("ldmatrix.sync.aligned.m8n8.x4.shared.b16 {%0,%1,%2,%3}, [%4];"
        : "=r"(r[0]), "=r"(r[1]), "=r"(r[2]), "=r"(r[3]) : "r"(addr));
}

__device__ __forceinline__ void mma16816(float* d, const uint32_t* a, const uint32_t* b) {
    asm volatile(
        "mma.sync.aligned.m16n8k16.row.col.f32.bf16.bf16.f32 "
        "{%0,%1,%2,%3}, {%4,%5,%6,%7}, {%8,%9}, {%0,%1,%2,%3};"
        : "+f"(d[0]), "+f"(d[1]), "+f"(d[2]), "+f"(d[3])
        : "r"(a[0]), "r"(a[1]), "r"(a[2]), "r"(a[3]), "r"(b[0]), "r"(b[1]));
}

// load one 128x32 fp32 operand tile -> split bf16 hi/lo in smem
__device__ __forceinline__ void load_op(const float* __restrict__ src, int ld,
                                        char* hi, char* lo, int tid)
{
    const int row = tid >> 1;
    const int kh = (tid & 1) << 4;            // 0 or 16
    const float* sp = src + (size_t)row * ld + kh;
    char* hp = hi + row * (GPITCH * 2) + kh * 2;
    char* lp = lo + row * (GPITCH * 2) + kh * 2;
#pragma unroll
    for (int q = 0; q < 4; ++q) {
        float4 v = *(const float4*)(sp + q * 4);
        uint32_t h01, l01, h23, l23;
        split2(v.x, v.y, h01, l01);
        split2(v.z, v.w, h23, l23);
        *(uint32_t*)(hp + q * 8)     = h01;
        *(uint32_t*)(hp + q * 8 + 4) = h23;
        *(uint32_t*)(lp + q * 8)     = l01;
        *(uint32_t*)(lp + q * 8 + 4) = l23;
    }
}

__global__ __launch_bounds__(256, 1) void mma_gemm(
    const float* __restrict__ A, const float* __restrict__ B,
    float* __restrict__ C, int M, int N, int K,
    long long sA, long long sB, long long sC)
{
    extern __shared__ char sm[];
    const uint32_t smb = smem_u32(sm);
    const int tid = threadIdx.x;
    const int wid = tid >> 5, lane = tid & 31;

    const float* Ab = A + (long long)blockIdx.z * sA;
    const float* Bb = B + (long long)blockIdx.z * sB;
    float*       Cb = C + (long long)blockIdx.z * sC;
    const int m0 = blockIdx.x * 128, n0 = blockIdx.y * 128;

    const int warp_m = wid >> 2, warp_n = wid & 3;     // 2 x 4 warps
    const int mbase = warp_m * 64, nbase = warp_n * 32;

    float acc[4][4][4];
#pragma unroll
    for (int i = 0; i < 4; i++)
#pragma unroll
        for (int j = 0; j < 4; j++)
#pragma unroll
            for (int q = 0; q < 4; q++) acc[i][j][q] = 0.f;

    const int nst = K >> 5;

    // prologue
    load_op(Ab + (size_t)m0 * K, K, sm, sm + TILE_BYTES, tid);
    load_op(Bb + (size_t)n0 * K, K, sm + 2 * TILE_BYTES, sm + 3 * TILE_BYTES, tid);

    // per-lane ldmatrix address components
    const int a_row = lane & 15;
    const int a_kad = (lane >> 4) << 3;                 // +8 cols for lanes 16-31
    const int b_row = (lane & 7) + ((lane & 16) >> 1);  // +8 rows for lanes 16-31
    const int b_kad = lane & 8;                         // +8 cols for lanes 8-15,24-31

    for (int s = 0; s < nst; ++s) {
        __syncthreads();
        const int buf = s & 1;
        if (s + 1 < nst) {
            const int k0 = (s + 1) << 5;
            char* st = sm + ((s + 1) & 1) * STAGE_BYTES;
            load_op(Ab + (size_t)m0 * K + k0, K, st, st + TILE_BYTES, tid);
            load_op(Bb + (size_t)n0 * K + k0, K, st + 2 * TILE_BYTES, st + 3 * TILE_BYTES, tid);
        }
        const uint32_t base = smb + buf * STAGE_BYTES;
#pragma unroll
        for (int ks = 0; ks < 2; ++ks) {
            uint32_t ah[4][4], al[4][4], bh[4][2], bl[4][2];
            const int acol = (ks << 4) + a_kad;
            const int bcol = (ks << 4) + b_kad;
#pragma unroll
            for (int am = 0; am < 4; ++am) {
                const uint32_t off = (mbase + am * 16 + a_row) * (GPITCH * 2) + acol * 2;
                ldm_x4(ah[am], base + off);
                ldm_x4(al[am], base + TILE_BYTES + off);
            }
#pragma unroll
            for (int bg = 0; bg < 2; ++bg) {
                uint32_t r[4];
                const uint32_t off = (nbase + bg * 16 + b_row) * (GPITCH * 2) + bcol * 2;
                ldm_x4(r, base + 2 * TILE_BYTES + off);
                bh[bg * 2][0] = r[0]; bh[bg * 2][1] = r[1];
                bh[bg * 2 + 1][0] = r[2]; bh[bg * 2 + 1][1] = r[3];
                ldm_x4(r, base + 3 * TILE_BYTES + off);
                bl[bg * 2][0] = r[0]; bl[bg * 2][1] = r[1];
                bl[bg * 2 + 1][0] = r[2]; bl[bg * 2 + 1][1] = r[3];
            }
#pragma unroll
            for (int am = 0; am < 4; ++am)
#pragma unroll
                for (int bn = 0; bn < 4; ++bn) {
                    mma16816(acc[am][bn], ah[am], bh[bn]);
                    mma16816(acc[am][bn], ah[am], bl[bn]);
                    mma16816(acc[am][bn], al[am], bh[bn]);
                }
        }
    }

    // epilogue: direct gmem float2 stores
    const int erow = lane >> 2, ecol = (lane & 3) << 1;
#pragma unroll
    for (int am = 0; am < 4; ++am) {
        const int r0 = m0 + mbase + am * 16 + erow;
#pragma unroll
        for (int bn = 0; bn < 4; ++bn) {
            const int c0 = n0 + nbase + bn * 8 + ecol;
            *(float2*)&Cb[(size_t)r0 * N + c0]       = make_float2(acc[am][bn][0], acc[am][bn][1]);
            *(float2*)&Cb[(size_t)(r0 + 8) * N + c0] = make_float2(acc[am][bn][2], acc[am][bn][3]);
        }
    }
}

// ---------------- concat router weights into [256, D] ----------------
__global__ void concat_kernel(const float* __restrict__ a, const float* __restrict__ b,
                              const float* __restrict__ c, const float* __restrict__ d)
{
    int i = blockIdx.x * 256 + threadIdx.x;
    int rt = i >> 16, rem = i & 65535;
    const float* src = (rt == 0) ? a : (rt == 1) ? b : (rt == 2) ? c : d;
    g_Wall[i] = src[rem];
}

// ---------------- router ----------------
__global__ void router_kernel(const float* __restrict__ importance)
{
    const int rt = blockIdx.x, b = blockIdx.y;
    const int k = (rt == 0) ? KC_ : KE_;
    __shared__ float wpart[8][64];
    __shared__ float w[64];
    const int tid = threadIdx.x, warp = tid >> 5, lane = tid & 31;

    float acc0 = 0.f, acc1 = 0.f;
    for (int s = warp; s < S_; s += 8) {
        const float* lp = g_logits + ((long long)(b * S_ + s)) * 256 + rt * 64;
        float v0 = lp[lane], v1 = lp[lane + 32];
        float mx = fmaxf(v0, v1);
#pragma unroll
        for (int off = 16; off; off >>= 1) mx = fmaxf(mx, __shfl_xor_sync(~0u, mx, off));
        float e0 = __expf(v0 - mx), e1 = __expf(v1 - mx);
        float smv = e0 + e1;
#pragma unroll
        for (int off = 16; off; off >>= 1) smv += __shfl_xor_sync(~0u, smv, off);
        float c = importance[b * S_ + s] / smv;
        acc0 += e0 * c;
        acc1 += e1 * c;
    }
    wpart[warp][lane]      = acc0;
    wpart[warp][lane + 32] = acc1;
    __syncthreads();
    if (tid < 64) {
        float t = 0.f;
#pragma unroll
        for (int wi = 0; wi < 8; wi++) t += wpart[wi][tid];
        w[tid] = t;
    }
    __syncthreads();
    if (tid == 0) {
        float tot = 0.f;
        for (int n = 0; n < 64; n++) tot += w[n];
        const float inv = 1.f / (tot + 1e-8f);
        float tw[16]; int ti[16]; bool used[64];
        for (int n = 0; n < 64; n++) used[n] = false;
        for (int kk = 0; kk < k; kk++) {
            float best = -1e30f; int bi = 0;
            for (int n = 0; n < 64; n++) {
                float v = w[n] * inv;
                if (!used[n] && v > best) { best = v; bi = n; }
            }
            used[bi] = true; tw[kk] = best; ti[kk] = bi;
        }
        float ts = 0.f;
        for (int kk = 0; kk < k; kk++) ts += tw[kk];
        const float inv2 = 1.f / (ts + 1e-8f);
        for (int kk = 0; kk < k; kk++) {
            g_tw[(rt * B_ + b) * 16 + kk] = tw[kk] * inv2;
            g_ti[(rt * B_ + b) * 16 + kk] = ti[kk];
        }
    }
}

// ---------------- mix compress -> g_sharedcT[b][r][d] (transposed) -----
// tile: 32 d x 32 r, smem transpose, both gmem sides float4-coalesced.
__global__ void mix_compressT_kernel(const float* __restrict__ cn)
{
    const int b = blockIdx.y;
    const int dt = blockIdx.x >> 3, rt = blockIdx.x & 7;   // d-tile (32), r-tile (8)
    const int d0 = dt * 32, r0 = rt * 32;
    __shared__ float cw[KC_]; __shared__ int ci[KC_];
    __shared__ float ts[32][33];
    if (threadIdx.x < KC_) {
        cw[threadIdx.x] = g_tw[(0 * B_ + b) * 16 + threadIdx.x];
        ci[threadIdx.x] = g_ti[(0 * B_ + b) * 16 + threadIdx.x];
    }
    __syncthreads();
    const int tid = threadIdx.x;
    const int dd = tid >> 3, rr = (tid & 7) << 2;          // read: [d][r4]
    float4 acc = {0.f, 0.f, 0.f, 0.f};
#pragma unroll
    for (int kk = 0; kk < KC_; kk++) {
        const float4 v = *(const float4*)(cn + ((size_t)ci[kk] * D_ + d0 + dd) * R_ + r0 + rr);
        const float wv = cw[kk];
        acc.x += wv * v.x; acc.y += wv * v.y; acc.z += wv * v.z; acc.w += wv * v.w;
    }
    ts[dd][rr] = acc.x; ts[dd][rr + 1] = acc.y; ts[dd][rr + 2] = acc.z; ts[dd][rr + 3] = acc.w;
    __syncthreads();
    const int rw = tid >> 3, dw = (tid & 7) << 2;          // write: [r][d4]
    float4 o = {ts[dw][rw], ts[dw + 1][rw], ts[dw + 2][rw], ts[dw + 3][rw]};
    *(float4*)(g_sharedcT + ((size_t)b * R_ + r0 + rw) * D_ + d0 + dw) = o;
}

// ---------------- mix expand -> g_eAllT[b][which*D + d][r] (transposed) --
// tile: 32 r x 32 d, smem transpose.
__global__ void mix_expandT_kernel(const float* __restrict__ pool)
{
    const int which = blockIdx.y, b = blockIdx.z;
    const int dt = blockIdx.x >> 3, rt = blockIdx.x & 7;
    const int d0 = dt * 32, r0 = rt * 32;
    const int rtr = which + 1;
    __shared__ float ew[KE_]; __shared__ int ei[KE_];
    __shared__ float ts[32][33];
    if (threadIdx.x < KE_) {
        ew[threadIdx.x] = g_tw[(rtr * B_ + b) * 16 + threadIdx.x];
        ei[threadIdx.x] = g_ti[(rtr * B_ + b) * 16 + threadIdx.x];
    }
    __syncthreads();
    const int tid = threadIdx.x;
    const int rr = tid >> 3, dd = (tid & 7) << 2;          // read pool[e][r][d4]
    float4 acc = {0.f, 0.f, 0.f, 0.f};
#pragma unroll
    for (int kk = 0; kk < KE_; kk++) {
        const float4 v = *(const float4*)(pool + ((size_t)ei[kk] * R_ + r0 + rr) * D_ + d0 + dd);
        const float wv = ew[kk];
        acc.x += wv * v.x; acc.y += wv * v.y; acc.z += wv * v.z; acc.w += wv * v.w;
    }
    ts[rr][dd] = acc.x; ts[rr][dd + 1] = acc.y; ts[rr][dd + 2] = acc.z; ts[rr][dd + 3] = acc.w;
    __syncthreads();
    const int dw = tid >> 3, rw = (tid & 7) << 2;          // write [d][r4]
    float4 o = {ts[rw][dw], ts[rw + 1][dw], ts[rw + 2][dw], ts[rw + 3][dw]};
    *(float4*)(g_eAllT + ((size_t)b * 3 * D_ + (size_t)which * D_ + d0 + dw) * R_ + r0 + rw) = o;
}

// ---------------- causal flash attention (fp32) ----------------
#define FA_PAD 68
__global__ __launch_bounds__(256) void flash_kernel(const float* __restrict__ qkv,
                                                    float* __restrict__ out)
{
    extern __shared__ float smf[];
    float* Qs  = smf;
    float* Ks  = Qs + 64 * FA_PAD;
    float* Vs  = Ks + 64 * FA_PAD;
    float* Pts = Vs + 64 * FA_PAD;

    const int tid = threadIdx.x;
    const int bh = blockIdx.y;
    const int b = bh >> 4, h = bh & 15;
    const int q0 = blockIdx.x * 64;
    const float* base = qkv + (long long)b * S_ * (3 * D_) + h * DH_;

    for (int i = tid; i < 64 * 16; i += 256) {
        const int r = i >> 4, d4 = (i & 15) << 2;
        float4 v = *(const float4*)(base + (long long)(q0 + r) * (3 * D_) + d4);
        Qs[(d4 + 0) * FA_PAD + r] = v.x; Qs[(d4 + 1) * FA_PAD + r] = v.y;
        Qs[(d4 + 2) * FA_PAD + r] = v.z; Qs[(d4 + 3) * FA_PAD + r] = v.w;
    }

    const int tx = tid & 15, ty = tid >> 4;
    float m[4], l[4], o[4][4];
#pragma unroll
    for (int i = 0; i < 4; i++) {
        m[i] = -1e30f; l[i] = 0.f;
#pragma unroll
        for (int j = 0; j < 4; j++) o[i][j] = 0.f;
    }
    const float scale = 0.125f;

    for (int k0 = 0; k0 <= q0; k0 += 64) {
        __syncthreads();
        for (int i = tid; i < 64 * 16; i += 256) {
            const int j = i >> 4, d4 = (i & 15) << 2;
            float4 kv = *(const float4*)(base + D_ + (long long)(k0 + j) * (3 * D_) + d4);
            Ks[(d4 + 0) * FA_PAD + j] = kv.x; Ks[(d4 + 1) * FA_PAD + j] = kv.y;
            Ks[(d4 + 2) * FA_PAD + j] = kv.z; Ks[(d4 + 3) * FA_PAD + j] = kv.w;
            float4 vv = *(const float4*)(base + 2 * D_ + (long long)(k0 + j) * (3 * D_) + d4);
            *(float4*)&Vs[j * FA_PAD + d4] = vv;
        }
        __syncthreads();

        float s[4][4];
#pragma unroll
        for (int i = 0; i < 4; i++)
#pragma unroll
            for (int j = 0; j < 4; j++) s[i][j] = 0.f;
#pragma unroll
        for (int d = 0; d < 64; ++d) {
            float4 q4 = *(const float4*)&Qs[d * FA_PAD + ty * 4];
            float4 k4 = *(const float4*)&Ks[d * FA_PAD + tx * 4];
            float qv[4] = {q4.x, q4.y, q4.z, q4.w};
            float kv[4] = {k4.x, k4.y, k4.z, k4.w};
#pragma unroll
            for (int i = 0; i < 4; i++)
#pragma unroll
                for (int j = 0; j < 4; j++)
                    s[i][j] = fmaf(qv[i], kv[j], s[i][j]);
        }
        const bool diag = (k0 == q0);
#pragma unroll
        for (int i = 0; i < 4; i++)
#pragma unroll
            for (int j = 0; j < 4; j++) {
                s[i][j] *= scale;
                if (diag && (tx * 4 + j > ty * 4 + i)) s[i][j] = -1e30f;
            }

#pragma unroll
        for (int i = 0; i < 4; i++) {
            float mx = fmaxf(fmaxf(s[i][0], s[i][1]), fmaxf(s[i][2], s[i][3]));
#pragma unroll
            for (int off = 8; off; off >>= 1)
                mx = fmaxf(mx, __shfl_xor_sync(~0u, mx, off));
            const float mn = fmaxf(m[i], mx);
            const float alpha = __expf(m[i] - mn);
            float ls = 0.f;
#pragma unroll
            for (int j = 0; j < 4; j++) {
                float p = __expf(s[i][j] - mn);
                s[i][j] = p; ls += p;
            }
#pragma unroll
            for (int off = 8; off; off >>= 1)
                ls += __shfl_xor_sync(~0u, ls, off);
            l[i] = l[i] * alpha + ls;
            m[i] = mn;
#pragma unroll
            for (int j = 0; j < 4; j++) o[i][j] *= alpha;
#pragma unroll
            for (int j = 0; j < 4; j++)
                Pts[(tx * 4 + j) * FA_PAD + ty * 4 + i] = s[i][j];
        }
        __syncthreads();

#pragma unroll
        for (int j = 0; j < 64; ++j) {
            float4 p4 = *(const float4*)&Pts[j * FA_PAD + ty * 4];
            float4 v4 = *(const float4*)&Vs[j * FA_PAD + tx * 4];
            float pv[4] = {p4.x, p4.y, p4.z, p4.w};
            float vv[4] = {v4.x, v4.y, v4.z, v4.w};
#pragma unroll
            for (int i = 0; i < 4; i++)
#pragma unroll
                for (int jj = 0; jj < 4; jj++)
                    o[i][jj] = fmaf(pv[i], vv[jj], o[i][jj]);
        }
    }

    float* op = out + (long long)b * S_ * D_ + (long long)q0 * D_ + h * DH_;
#pragma unroll
    for (int i = 0; i < 4; i++) {
        const float inv = 1.f / l[i];
        float4 c = {o[i][0] * inv, o[i][1] * inv, o[i][2] * inv, o[i][3] * inv};
        *(float4*)&op[(long long)(ty * 4 + i) * D_ + tx * 4] = c;
    }
}

// ---------------- launch ----------------
extern "C" void kernel_launch(void* const* d_in, const int* in_sizes, int n_in,
                              void* d_out, int out_size)
{
    const float* x    = (const float*)d_in[0];
    const float* imp  = (const float*)d_in[1];
    const float* Wc   = (const float*)d_in[2];
    const float* Wq   = (const float*)d_in[3];
    const float* Wk   = (const float*)d_in[4];
    const float* Wv   = (const float*)d_in[5];
    const float* cn   = (const float*)d_in[6];
    const float* pool = (const float*)d_in[7];
    const float* WO   = (const float*)d_in[8];
    float* out = (float*)d_out;

    float *pWall, *pLog, *pScT, *pH, *pET, *pQKV, *pAO;
    cudaGetSymbolAddress((void**)&pWall, g_Wall);
    cudaGetSymbolAddress((void**)&pLog,  g_logits);
    cudaGetSymbolAddress((void**)&pScT,  g_sharedcT);
    cudaGetSymbolAddress((void**)&pH,    g_h);
    cudaGetSymbolAddress((void**)&pET,   g_eAllT);
    cudaGetSymbolAddress((void**)&pQKV,  g_qkv);
    cudaGetSymbolAddress((void**)&pAO,   g_aout);

    cudaFuncSetAttribute(mma_gemm, cudaFuncAttributeMaxDynamicSharedMemorySize, GEMM_SMEM);

    // 1. concat router weights -> [256][D]
    concat_kernel<<<1024, 256>>>(Wc, Wq, Wk, Wv);
    // 2. routing logits: [8192,1024] @ [256,1024]^T
    mma_gemm<<<dim3(64, 2, 1), 256, GEMM_SMEM>>>(x, pWall, pLog, 8192, 256, 1024, 0, 0, 0);
    // 3. routers
    router_kernel<<<dim3(4, 8), 256>>>(imp);
    // 4. mix compress neurons -> sharedc^T [b][r][d]
    mix_compressT_kernel<<<dim3(256, 8), 256>>>(cn);
    // 5. h = x @ sharedc  ==  x[s][d] @ (sharedcT[r][d])^T  (batched)
    mma_gemm<<<dim3(8, 2, 8), 256, GEMM_SMEM>>>(x, pScT, pH, 1024, 256, 1024,
        (long long)S_ * D_, (long long)R_ * D_, (long long)S_ * R_);
    // 6. mix expand pool -> eAll^T [b][3D][r]
    mix_expandT_kernel<<<dim3(256, 3, 8), 256>>>(pool);
    // 7. QKV = h[s][r] @ (eAllT[3D][r])^T  (batched)
    mma_gemm<<<dim3(8, 24, 8), 256, GEMM_SMEM>>>(pH, pET, pQKV, 1024, 3 * D_, 256,
        (long long)S_ * R_, (long long)3 * D_ * R_, (long long)S_ * 3 * D_);
    // 8. causal flash attention
    const size_t fa_smem = 4 * 64 * FA_PAD * sizeof(float);
    cudaFuncSetAttribute(flash_kernel, cudaFuncAttributeMaxDynamicSharedMemorySize,
                         (int)fa_smem);
    flash_kernel<<<dim3(16, 128), 256, fa_smem>>>(pQKV, pAO);
    // 9. output projection: aout[s][d] @ (W_O[e][d])^T
    mma_gemm<<<dim3(64, 8, 1), 256, GEMM_SMEM>>>(pAO, WO, out, 8192, 1024, 1024, 0, 0, 0);
}

// round 4
// speedup vs baseline: 1.6050x; 1.3466x over previous
#include <cuda_runtime.h>
#include <cuda_bf16.h>
#include <cstdint>

// ---------------- problem constants ----------------
#define B_  8
#define S_  1024
#define D_  1024
#define H_  16
#define DH_ 64
#define R_  256
#define NC_ 64
#define NE_ 64
#define KC_ 16
#define KE_ 8

// ---------------- scratch (device globals; no allocation allowed) ----------
__device__ float g_Wall[256 * D_];                 // [256][D]
__device__ float g_logits[B_ * S_ * 256];
__device__ float g_tw[4 * B_ * 16];
__device__ int   g_ti[4 * B_ * 16];
__device__ float g_sharedcT[B_ * R_ * D_];         // [b][r][d]
__device__ float g_h[B_ * S_ * R_];                // [b][s][r]
__device__ float g_eAllT[B_ * 3 * D_ * R_];        // [b][3D][r]
__device__ float g_qkv[B_ * S_ * 3 * D_];          // [b][s][3D]
__device__ float g_aout[B_ * S_ * D_];             // [b][s][D]

// =======================================================================
// shared mma helpers
// =======================================================================
__device__ __forceinline__ uint32_t smem_u32(const void* p) {
    uint32_t a;
    asm("{ .reg .u64 t; cvta.to.shared.u64 t, %1; cvt.u32.u64 %0, t; }"
        : "=r"(a) : "l"(p));
    return a;
}

__device__ __forceinline__ void split2(float x, float y, uint32_t& hi, uint32_t& lo) {
    __nv_bfloat16 hx = __float2bfloat16(x);
    __nv_bfloat16 hy = __float2bfloat16(y);
    __nv_bfloat16 lx = __float2bfloat16(x - __bfloat162float(hx));
    __nv_bfloat16 ly = __float2bfloat16(y - __bfloat162float(hy));
    hi = ((uint32_t)__bfloat16_as_ushort(hy) << 16) | __bfloat16_as_ushort(hx);
    lo = ((uint32_t)__bfloat16_as_ushort(ly) << 16) | __bfloat16_as_ushort(lx);
}

__device__ __forceinline__ void ldm_x4(uint32_t* r, uint32_t addr) {
    asm volatile("ldmatrix.sync.aligned.m8n8.x4.shared.b16 {%0,%1,%2,%3}, [%4];"
        : "=r"(r[0]), "=r"(r[1]), "=r"(r[2]), "=r"(r[3]) : "r"(addr));
}
__device__ __forceinline__ void ldm_x4t(uint32_t* r, uint32_t addr) {
    asm volatile("ldmatrix.sync.aligned.m8n8.x4.trans.shared.b16 {%0,%1,%2,%3}, [%4];"
        : "=r"(r[0]), "=r"(r[1]), "=r"(r[2]), "=r"(r[3]) : "r"(addr));
}

__device__ __forceinline__ void mma16816(float* d, const uint32_t* a, const uint32_t* b) {
    asm volatile(
        "mma.sync.aligned.m16n8k16.row.col.f32.bf16.bf16.f32 "
        "{%0,%1,%2,%3}, {%4,%5,%6,%7}, {%8,%9}, {%0,%1,%2,%3};"
        : "+f"(d[0]), "+f"(d[1]), "+f"(d[2]), "+f"(d[3])
        : "r"(a[0]), "r"(a[1]), "r"(a[2]), "r"(a[3]), "r"(b[0]), "r"(b[1]));
}

// =======================================================================
// split-bf16 mma GEMM:  C[M,N] = A[M,K] @ B[N,K]^T
// =======================================================================
#define GPITCH 40
#define TILE_BYTES (128 * GPITCH * 2)
#define STAGE_BYTES (4 * TILE_BYTES)
#define GEMM_SMEM (2 * STAGE_BYTES)

__device__ __forceinline__ void load_op(const float* __restrict__ src, int ld,
                                        char* hi, char* lo, int tid)
{
    const int row = tid >> 1;
    const int kh = (tid & 1) << 4;
    const float* sp = src + (size_t)row * ld + kh;
    char* hp = hi + row * (GPITCH * 2) + kh * 2;
    char* lp = lo + row * (GPITCH * 2) + kh * 2;
#pragma unroll
    for (int q = 0; q < 4; ++q) {
        float4 v = *(const float4*)(sp + q * 4);
        uint32_t h01, l01, h23, l23;
        split2(v.x, v.y, h01, l01);
        split2(v.z, v.w, h23, l23);
        *(uint32_t*)(hp + q * 8)     = h01;
        *(uint32_t*)(hp + q * 8 + 4) = h23;
        *(uint32_t*)(lp + q * 8)     = l01;
        *(uint32_t*)(lp + q * 8 + 4) = l23;
    }
}

__global__ __launch_bounds__(256, 1) void mma_gemm(
    const float* __restrict__ A, const float* __restrict__ B,
    float* __restrict__ C, int M, int N, int K,
    long long sA, long long sB, long long sC)
{
    extern __shared__ char sm[];
    const uint32_t smb = smem_u32(sm);
    const int tid = threadIdx.x;
    const int wid = tid >> 5, lane = tid & 31;

    const float* Ab = A + (long long)blockIdx.z * sA;
    const float* Bb = B + (long long)blockIdx.z * sB;
    float*       Cb = C + (long long)blockIdx.z * sC;
    const int m0 = blockIdx.x * 128, n0 = blockIdx.y * 128;

    const int warp_m = wid >> 2, warp_n = wid & 3;
    const int mbase = warp_m * 64, nbase = warp_n * 32;

    float acc[4][4][4];
#pragma unroll
    for (int i = 0; i < 4; i++)
#pragma unroll
        for (int j = 0; j < 4; j++)
#pragma unroll
            for (int q = 0; q < 4; q++) acc[i][j][q] = 0.f;

    const int nst = K >> 5;

    load_op(Ab + (size_t)m0 * K, K, sm, sm + TILE_BYTES, tid);
    load_op(Bb + (size_t)n0 * K, K, sm + 2 * TILE_BYTES, sm + 3 * TILE_BYTES, tid);

    const int a_row = lane & 15;
    const int a_kad = (lane >> 4) << 3;
    const int b_row = (lane & 7) + ((lane & 16) >> 1);
    const int b_kad = lane & 8;

    for (int s = 0; s < nst; ++s) {
        __syncthreads();
        const int buf = s & 1;
        if (s + 1 < nst) {
            const int k0 = (s + 1) << 5;
            char* st = sm + ((s + 1) & 1) * STAGE_BYTES;
            load_op(Ab + (size_t)m0 * K + k0, K, st, st + TILE_BYTES, tid);
            load_op(Bb + (size_t)n0 * K + k0, K, st + 2 * TILE_BYTES, st + 3 * TILE_BYTES, tid);
        }
        const uint32_t base = smb + buf * STAGE_BYTES;
#pragma unroll
        for (int ks = 0; ks < 2; ++ks) {
            uint32_t ah[4][4], al[4][4], bh[4][2], bl[4][2];
            const int acol = (ks << 4) + a_kad;
            const int bcol = (ks << 4) + b_kad;
#pragma unroll
            for (int am = 0; am < 4; ++am) {
                const uint32_t off = (mbase + am * 16 + a_row) * (GPITCH * 2) + acol * 2;
                ldm_x4(ah[am], base + off);
                ldm_x4(al[am], base + TILE_BYTES + off);
            }
#pragma unroll
            for (int bg = 0; bg < 2; ++bg) {
                uint32_t r[4];
                const uint32_t off = (nbase + bg * 16 + b_row) * (GPITCH * 2) + bcol * 2;
                ldm_x4(r, base + 2 * TILE_BYTES + off);
                bh[bg * 2][0] = r[0]; bh[bg * 2][1] = r[1];
                bh[bg * 2 + 1][0] = r[2]; bh[bg * 2 + 1][1] = r[3];
                ldm_x4(r, base + 3 * TILE_BYTES + off);
                bl[bg * 2][0] = r[0]; bl[bg * 2][1] = r[1];
                bl[bg * 2 + 1][0] = r[2]; bl[bg * 2 + 1][1] = r[3];
            }
#pragma unroll
            for (int am = 0; am < 4; ++am)
#pragma unroll
                for (int bn = 0; bn < 4; ++bn) {
                    mma16816(acc[am][bn], ah[am], bh[bn]);
                    mma16816(acc[am][bn], ah[am], bl[bn]);
                    mma16816(acc[am][bn], al[am], bh[bn]);
                }
        }
    }

    const int erow = lane >> 2, ecol = (lane & 3) << 1;
#pragma unroll
    for (int am = 0; am < 4; ++am) {
        const int r0 = m0 + mbase + am * 16 + erow;
#pragma unroll
        for (int bn = 0; bn < 4; ++bn) {
            const int c0 = n0 + nbase + bn * 8 + ecol;
            *(float2*)&Cb[(size_t)r0 * N + c0]       = make_float2(acc[am][bn][0], acc[am][bn][1]);
            *(float2*)&Cb[(size_t)(r0 + 8) * N + c0] = make_float2(acc[am][bn][2], acc[am][bn][3]);
        }
    }
}

// ---------------- concat router weights ----------------
__global__ void concat_kernel(const float* __restrict__ a, const float* __restrict__ b,
                              const float* __restrict__ c, const float* __restrict__ d)
{
    int i = blockIdx.x * 256 + threadIdx.x;
    int rt = i >> 16, rem = i & 65535;
    const float* src = (rt == 0) ? a : (rt == 1) ? b : (rt == 2) ? c : d;
    g_Wall[i] = src[rem];
}

// ---------------- router ----------------
__global__ void router_kernel(const float* __restrict__ importance)
{
    const int rt = blockIdx.x, b = blockIdx.y;
    const int k = (rt == 0) ? KC_ : KE_;
    __shared__ float wpart[8][64];
    __shared__ float w[64];
    const int tid = threadIdx.x, warp = tid >> 5, lane = tid & 31;

    float acc0 = 0.f, acc1 = 0.f;
    for (int s = warp; s < S_; s += 8) {
        const float* lp = g_logits + ((long long)(b * S_ + s)) * 256 + rt * 64;
        float v0 = lp[lane], v1 = lp[lane + 32];
        float mx = fmaxf(v0, v1);
#pragma unroll
        for (int off = 16; off; off >>= 1) mx = fmaxf(mx, __shfl_xor_sync(~0u, mx, off));
        float e0 = __expf(v0 - mx), e1 = __expf(v1 - mx);
        float smv = e0 + e1;
#pragma unroll
        for (int off = 16; off; off >>= 1) smv += __shfl_xor_sync(~0u, smv, off);
        float c = importance[b * S_ + s] / smv;
        acc0 += e0 * c;
        acc1 += e1 * c;
    }
    wpart[warp][lane]      = acc0;
    wpart[warp][lane + 32] = acc1;
    __syncthreads();
    if (tid < 64) {
        float t = 0.f;
#pragma unroll
        for (int wi = 0; wi < 8; wi++) t += wpart[wi][tid];
        w[tid] = t;
    }
    __syncthreads();
    if (tid == 0) {
        float tot = 0.f;
        for (int n = 0; n < 64; n++) tot += w[n];
        const float inv = 1.f / (tot + 1e-8f);
        float tw[16]; int ti[16]; bool used[64];
        for (int n = 0; n < 64; n++) used[n] = false;
        for (int kk = 0; kk < k; kk++) {
            float best = -1e30f; int bi = 0;
            for (int n = 0; n < 64; n++) {
                float v = w[n] * inv;
                if (!used[n] && v > best) { best = v; bi = n; }
            }
            used[bi] = true; tw[kk] = best; ti[kk] = bi;
        }
        float ts = 0.f;
        for (int kk = 0; kk < k; kk++) ts += tw[kk];
        const float inv2 = 1.f / (ts + 1e-8f);
        for (int kk = 0; kk < k; kk++) {
            g_tw[(rt * B_ + b) * 16 + kk] = tw[kk] * inv2;
            g_ti[(rt * B_ + b) * 16 + kk] = ti[kk];
        }
    }
}

// ---------------- mix compress -> g_sharedcT[b][r][d] -----
__global__ void mix_compressT_kernel(const float* __restrict__ cn)
{
    const int b = blockIdx.y;
    const int dt = blockIdx.x >> 3, rt = blockIdx.x & 7;
    const int d0 = dt * 32, r0 = rt * 32;
    __shared__ float cw[KC_]; __shared__ int ci[KC_];
    __shared__ float ts[32][33];
    if (threadIdx.x < KC_) {
        cw[threadIdx.x] = g_tw[(0 * B_ + b) * 16 + threadIdx.x];
        ci[threadIdx.x] = g_ti[(0 * B_ + b) * 16 + threadIdx.x];
    }
    __syncthreads();
    const int tid = threadIdx.x;
    const int dd = tid >> 3, rr = (tid & 7) << 2;
    float4 acc = {0.f, 0.f, 0.f, 0.f};
#pragma unroll
    for (int kk = 0; kk < KC_; kk++) {
        const float4 v = *(const float4*)(cn + ((size_t)ci[kk] * D_ + d0 + dd) * R_ + r0 + rr);
        const float wv = cw[kk];
        acc.x += wv * v.x; acc.y += wv * v.y; acc.z += wv * v.z; acc.w += wv * v.w;
    }
    ts[dd][rr] = acc.x; ts[dd][rr + 1] = acc.y; ts[dd][rr + 2] = acc.z; ts[dd][rr + 3] = acc.w;
    __syncthreads();
    const int rw = tid >> 3, dw = (tid & 7) << 2;
    float4 o = {ts[dw][rw], ts[dw + 1][rw], ts[dw + 2][rw], ts[dw + 3][rw]};
    *(float4*)(g_sharedcT + ((size_t)b * R_ + r0 + rw) * D_ + d0 + dw) = o;
}

// ---------------- mix expand -> g_eAllT[b][which*D + d][r] --
__global__ void mix_expandT_kernel(const float* __restrict__ pool)
{
    const int which = blockIdx.y, b = blockIdx.z;
    const int dt = blockIdx.x >> 3, rt = blockIdx.x & 7;
    const int d0 = dt * 32, r0 = rt * 32;
    const int rtr = which + 1;
    __shared__ float ew[KE_]; __shared__ int ei[KE_];
    __shared__ float ts[32][33];
    if (threadIdx.x < KE_) {
        ew[threadIdx.x] = g_tw[(rtr * B_ + b) * 16 + threadIdx.x];
        ei[threadIdx.x] = g_ti[(rtr * B_ + b) * 16 + threadIdx.x];
    }
    __syncthreads();
    const int tid = threadIdx.x;
    const int rr = tid >> 3, dd = (tid & 7) << 2;
    float4 acc = {0.f, 0.f, 0.f, 0.f};
#pragma unroll
    for (int kk = 0; kk < KE_; kk++) {
        const float4 v = *(const float4*)(pool + ((size_t)ei[kk] * R_ + r0 + rr) * D_ + d0 + dd);
        const float wv = ew[kk];
        acc.x += wv * v.x; acc.y += wv * v.y; acc.z += wv * v.z; acc.w += wv * v.w;
    }
    ts[rr][dd] = acc.x; ts[rr][dd + 1] = acc.y; ts[rr][dd + 2] = acc.z; ts[rr][dd + 3] = acc.w;
    __syncthreads();
    const int dw = tid >> 3, rw = (tid & 7) << 2;
    float4 o = {ts[rw][dw], ts[rw + 1][dw], ts[rw + 2][dw], ts[rw + 3][dw]};
    *(float4*)(g_eAllT + ((size_t)b * 3 * D_ + (size_t)which * D_ + d0 + dw) * R_ + r0 + rw) = o;
}

// =======================================================================
// flash attention via mma.sync (split-bf16 S and PV)
// CTA: 128 q-rows x 1 (b,h); 8 warps x 16 rows; k-tiles of 64.
// =======================================================================
#define FP 72                        // smem pitch (bf16 elems); 144B rows
#define FQHI 0
#define FQLO (128 * FP)
#define FKHI (256 * FP)
#define FKLO (FKHI + 64 * FP)
#define FVHI (FKLO + 64 * FP)
#define FVLO (FVHI + 64 * FP)
#define FLASH_SMEM ((FVLO + 64 * FP) * 2)      // 73728 bytes
#define SC2L 0.18033688011112042f              // 0.125 * log2(e)

__global__ __launch_bounds__(256, 1) void flash_mma_kernel(
    const float* __restrict__ qkv, float* __restrict__ out)
{
    extern __shared__ char smc[];
    const uint32_t smb = smem_u32(smc);
    const int tid = threadIdx.x, w = tid >> 5, lane = tid & 31;
    const int b = blockIdx.y >> 4, h = blockIdx.y & 15;
    const int q0 = blockIdx.x * 128;
    const float* base = qkv + (size_t)b * S_ * (3 * D_) + h * DH_;

    // ---- load Q tile (128x64) -> split bf16 hi/lo smem ----
    {
        const int r = tid >> 1, c0 = (tid & 1) << 5;
        const float* qp = base + (size_t)(q0 + r) * (3 * D_) + c0;
#pragma unroll
        for (int q = 0; q < 8; ++q) {
            float4 v = *(const float4*)(qp + q * 4);
            uint32_t h01, l01, h23, l23;
            split2(v.x, v.y, h01, l01);
            split2(v.z, v.w, h23, l23);
            const uint32_t off = (uint32_t)(r * FP + c0 + q * 4);
            *(uint32_t*)(smc + 2 * (FQHI + off))     = h01;
            *(uint32_t*)(smc + 2 * (FQHI + off) + 4) = h23;
            *(uint32_t*)(smc + 2 * (FQLO + off))     = l01;
            *(uint32_t*)(smc + 2 * (FQLO + off) + 4) = l23;
        }
    }

    float sacc[8][4], oacc[8][4];
    float m0v = -1e30f, m1v = -1e30f, l0v = 0.f, l1v = 0.f;
#pragma unroll
    for (int t = 0; t < 8; t++)
#pragma unroll
        for (int e = 0; e < 4; e++) oacc[t][e] = 0.f;

    const int a_row = lane & 15;
    const int a_kad = (lane >> 4) << 3;
    const int b_row = (lane & 7) + ((lane & 16) >> 1);
    const int b_kad = lane & 8;
    const int qwarp = q0 + w * 16;
    const int r0 = lane >> 2;
    const int c0l = (lane & 3) << 1;

    const int kend = q0 + 128;
    for (int k0 = 0; k0 < kend; k0 += 64) {
        __syncthreads();
        // ---- load K,V tiles (64x64 each) ----
        {
            const int jr = tid >> 2, cc = (tid & 3) << 4;
            const float* kp = base + D_ + (size_t)(k0 + jr) * (3 * D_) + cc;
            const float* vp = base + 2 * D_ + (size_t)(k0 + jr) * (3 * D_) + cc;
#pragma unroll
            for (int q = 0; q < 4; ++q) {
                float4 v = *(const float4*)(kp + q * 4);
                uint32_t h01, l01, h23, l23;
                split2(v.x, v.y, h01, l01);
                split2(v.z, v.w, h23, l23);
                const uint32_t off = (uint32_t)(jr * FP + cc + q * 4);
                *(uint32_t*)(smc + 2 * (FKHI + off))     = h01;
                *(uint32_t*)(smc + 2 * (FKHI + off) + 4) = h23;
                *(uint32_t*)(smc + 2 * (FKLO + off))     = l01;
                *(uint32_t*)(smc + 2 * (FKLO + off) + 4) = l23;
            }
#pragma unroll
            for (int q = 0; q < 4; ++q) {
                float4 v = *(const float4*)(vp + q * 4);
                uint32_t h01, l01, h23, l23;
                split2(v.x, v.y, h01, l01);
                split2(v.z, v.w, h23, l23);
                const uint32_t off = (uint32_t)(jr * FP + cc + q * 4);
                *(uint32_t*)(smc + 2 * (FVHI + off))     = h01;
                *(uint32_t*)(smc + 2 * (FVHI + off) + 4) = h23;
                *(uint32_t*)(smc + 2 * (FVLO + off))     = l01;
                *(uint32_t*)(smc + 2 * (FVLO + off) + 4) = l23;
            }
        }
        __syncthreads();

        if (k0 > qwarp + 15) continue;     // fully masked for this warp

        // ---- S = Q K^T (split 3-term) ----
#pragma unroll
        for (int t = 0; t < 8; t++)
#pragma unroll
            for (int e = 0; e < 4; e++) sacc[t][e] = 0.f;
#pragma unroll
        for (int kk = 0; kk < 4; ++kk) {
            uint32_t qh[4], ql[4];
            const uint32_t qoff = 2 * (uint32_t)((w * 16 + a_row) * FP + kk * 16 + a_kad);
            ldm_x4(qh, smb + 2 * FQHI + qoff);
            ldm_x4(ql, smb + 2 * FQLO + qoff);
#pragma unroll
            for (int jt = 0; jt < 4; ++jt) {
                uint32_t kh[4], kl[4];
                const uint32_t koff = 2 * (uint32_t)((jt * 16 + b_row) * FP + kk * 16 + b_kad);
                ldm_x4(kh, smb + 2 * FKHI + koff);
                ldm_x4(kl, smb + 2 * FKLO + koff);
                mma16816(sacc[jt * 2],     qh, kh);
                mma16816(sacc[jt * 2 + 1], qh, kh + 2);
                mma16816(sacc[jt * 2],     qh, kl);
                mma16816(sacc[jt * 2 + 1], qh, kl + 2);
                mma16816(sacc[jt * 2],     ql, kh);
                mma16816(sacc[jt * 2 + 1], ql, kh + 2);
            }
        }

        // ---- causal mask (only needed on diagonal-overlap tiles) ----
        if (k0 + 63 > qwarp) {
#pragma unroll
            for (int t = 0; t < 8; t++) {
                const int kg = k0 + t * 8 + c0l;
#pragma unroll
                for (int e = 0; e < 4; e++) {
                    const int kge = kg + (e & 1);
                    const int qg = qwarp + r0 + ((e >> 1) << 3);
                    if (kge > qg) sacc[t][e] = -1e30f;
                }
            }
        }

        // ---- online softmax ----
        float mx0 = -1e30f, mx1 = -1e30f;
#pragma unroll
        for (int t = 0; t < 8; t++) {
            mx0 = fmaxf(mx0, fmaxf(sacc[t][0], sacc[t][1]));
            mx1 = fmaxf(mx1, fmaxf(sacc[t][2], sacc[t][3]));
        }
        mx0 = fmaxf(mx0, __shfl_xor_sync(~0u, mx0, 1));
        mx0 = fmaxf(mx0, __shfl_xor_sync(~0u, mx0, 2));
        mx1 = fmaxf(mx1, __shfl_xor_sync(~0u, mx1, 1));
        mx1 = fmaxf(mx1, __shfl_xor_sync(~0u, mx1, 2));
        const float mn0 = fmaxf(m0v, mx0), mn1 = fmaxf(m1v, mx1);
        const float al0 = exp2f((m0v - mn0) * SC2L);
        const float al1 = exp2f((m1v - mn1) * SC2L);
        float sum0 = 0.f, sum1 = 0.f;
        uint32_t ph[8][2], pl[8][2];
#pragma unroll
        for (int t = 0; t < 8; t++) {
            float p0 = exp2f((sacc[t][0] - mn0) * SC2L);
            float p1 = exp2f((sacc[t][1] - mn0) * SC2L);
            float p2 = exp2f((sacc[t][2] - mn1) * SC2L);
            float p3 = exp2f((sacc[t][3] - mn1) * SC2L);
            sum0 += p0 + p1; sum1 += p2 + p3;
            split2(p0, p1, ph[t][0], pl[t][0]);
            split2(p2, p3, ph[t][1], pl[t][1]);
        }
        sum0 += __shfl_xor_sync(~0u, sum0, 1);
        sum0 += __shfl_xor_sync(~0u, sum0, 2);
        sum1 += __shfl_xor_sync(~0u, sum1, 1);
        sum1 += __shfl_xor_sync(~0u, sum1, 2);
        l0v = l0v * al0 + sum0;
        l1v = l1v * al1 + sum1;
        m0v = mn0; m1v = mn1;
#pragma unroll
        for (int t = 0; t < 8; t++) {
            oacc[t][0] *= al0; oacc[t][1] *= al0;
            oacc[t][2] *= al1; oacc[t][3] *= al1;
        }

        // ---- O += P V (split 3-term); V via ldmatrix.trans ----
#pragma unroll
        for (int g = 0; g < 4; ++g) {
            uint32_t Ah[4] = {ph[2 * g][0], ph[2 * g][1], ph[2 * g + 1][0], ph[2 * g + 1][1]};
            uint32_t Al[4] = {pl[2 * g][0], pl[2 * g][1], pl[2 * g + 1][0], pl[2 * g + 1][1]};
#pragma unroll
            for (int dp = 0; dp < 4; ++dp) {
                uint32_t vh[4], vl[4];
                const uint32_t voff = 2 * (uint32_t)((g * 16 + (lane & 15)) * FP
                                                     + dp * 16 + ((lane >> 4) << 3));
                ldm_x4t(vh, smb + 2 * FVHI + voff);
                ldm_x4t(vl, smb + 2 * FVLO + voff);
                mma16816(oacc[dp * 2],     Ah, vh);
                mma16816(oacc[dp * 2 + 1], Ah, vh + 2);
                mma16816(oacc[dp * 2],     Al, vh);
                mma16816(oacc[dp * 2 + 1], Al, vh + 2);
                mma16816(oacc[dp * 2],     Ah, vl);
                mma16816(oacc[dp * 2 + 1], Ah, vl + 2);
            }
        }
    }

    // ---- write output ----
    const float inv0 = 1.f / l0v, inv1 = 1.f / l1v;
    float* op = out + (size_t)b * S_ * D_ + (size_t)h * DH_;
    const int row0 = q0 + w * 16 + r0;
#pragma unroll
    for (int t = 0; t < 8; t++) {
        const int c = t * 8 + c0l;
        *(float2*)&op[(size_t)row0 * D_ + c] =
            make_float2(oacc[t][0] * inv0, oacc[t][1] * inv0);
        *(float2*)&op[(size_t)(row0 + 8) * D_ + c] =
            make_float2(oacc[t][2] * inv1, oacc[t][3] * inv1);
    }
}

// ---------------- launch ----------------
extern "C" void kernel_launch(void* const* d_in, const int* in_sizes, int n_in,
                              void* d_out, int out_size)
{
    const float* x    = (const float*)d_in[0];
    const float* imp  = (const float*)d_in[1];
    const float* Wc   = (const float*)d_in[2];
    const float* Wq   = (const float*)d_in[3];
    const float* Wk   = (const float*)d_in[4];
    const float* Wv   = (const float*)d_in[5];
    const float* cn   = (const float*)d_in[6];
    const float* pool = (const float*)d_in[7];
    const float* WO   = (const float*)d_in[8];
    float* out = (float*)d_out;

    float *pWall, *pLog, *pScT, *pH, *pET, *pQKV, *pAO;
    cudaGetSymbolAddress((void**)&pWall, g_Wall);
    cudaGetSymbolAddress((void**)&pLog,  g_logits);
    cudaGetSymbolAddress((void**)&pScT,  g_sharedcT);
    cudaGetSymbolAddress((void**)&pH,    g_h);
    cudaGetSymbolAddress((void**)&pET,   g_eAllT);
    cudaGetSymbolAddress((void**)&pQKV,  g_qkv);
    cudaGetSymbolAddress((void**)&pAO,   g_aout);

    cudaFuncSetAttribute(mma_gemm, cudaFuncAttributeMaxDynamicSharedMemorySize, GEMM_SMEM);
    cudaFuncSetAttribute(flash_mma_kernel, cudaFuncAttributeMaxDynamicSharedMemorySize,
                         FLASH_SMEM);

    // 1. concat router weights
    concat_kernel<<<1024, 256>>>(Wc, Wq, Wk, Wv);
    // 2. routing logits
    mma_gemm<<<dim3(64, 2, 1), 256, GEMM_SMEM>>>(x, pWall, pLog, 8192, 256, 1024, 0, 0, 0);
    // 3. routers
    router_kernel<<<dim3(4, 8), 256>>>(imp);
    // 4. mix compress -> sharedc^T
    mix_compressT_kernel<<<dim3(256, 8), 256>>>(cn);
    // 5. h = x @ sharedc
    mma_gemm<<<dim3(8, 2, 8), 256, GEMM_SMEM>>>(x, pScT, pH, 1024, 256, 1024,
        (long long)S_ * D_, (long long)R_ * D_, (long long)S_ * R_);
    // 6. mix expand -> eAll^T
    mix_expandT_kernel<<<dim3(256, 3, 8), 256>>>(pool);
    // 7. QKV = h @ eAll
    mma_gemm<<<dim3(8, 24, 8), 256, GEMM_SMEM>>>(pH, pET, pQKV, 1024, 3 * D_, 256,
        (long long)S_ * R_, (long long)3 * D_ * R_, (long long)S_ * 3 * D_);
    // 8. flash attention (mma)
    flash_mma_kernel<<<dim3(8, 128), 256, FLASH_SMEM>>>(pQKV, pAO);
    // 9. output projection
    mma_gemm<<<dim3(64, 8, 1), 256, GEMM_SMEM>>>(pAO, WO, out, 8192, 1024, 1024, 0, 0, 0);
}

// round 5
// speedup vs baseline: 2.2521x; 1.4032x over previous
#include <cuda_runtime.h>
#include <cuda_bf16.h>
#include <cstdint>

// ---------------- problem constants ----------------
#define B_  8
#define S_  1024
#define D_  1024
#define H_  16
#define DH_ 64
#define R_  256
#define KC_ 16
#define KE_ 8

// ---------------- scratch (device globals) ----------
__device__ float g_logits[B_ * S_ * 256];
__device__ float g_tw[4 * B_ * 16];
__device__ int   g_ti[4 * B_ * 16];
__device__ __nv_bfloat16 g_xhi[B_ * S_ * D_],  g_xlo[B_ * S_ * D_];
__device__ __nv_bfloat16 g_whi[256 * D_],      g_wlo[256 * D_];
__device__ __nv_bfloat16 g_schi[B_ * R_ * D_], g_sclo[B_ * R_ * D_];     // [b][r][d]
__device__ __nv_bfloat16 g_hhi[B_ * S_ * R_],  g_hlo[B_ * S_ * R_];      // [b][s][r]
__device__ __nv_bfloat16 g_ehi[B_ * 3 * D_ * R_], g_elo[B_ * 3 * D_ * R_]; // [b][3D][r]
__device__ __nv_bfloat16 g_qhi[B_ * S_ * 3 * D_], g_qlo[B_ * S_ * 3 * D_]; // [b][s][3D]
__device__ __nv_bfloat16 g_aohi[B_ * S_ * D_], g_aolo[B_ * S_ * D_];     // [b][s][D]
__device__ __nv_bfloat16 g_wohi[D_ * D_],      g_wolo[D_ * D_];

// ---------------- helpers ----------------
__device__ __forceinline__ uint32_t smem_u32(const void* p) {
    uint32_t a;
    asm("{ .reg .u64 t; cvta.to.shared.u64 t, %1; cvt.u32.u64 %0, t; }"
        : "=r"(a) : "l"(p));
    return a;
}
__device__ __forceinline__ void split2(float x, float y, uint32_t& hi, uint32_t& lo) {
    __nv_bfloat16 hx = __float2bfloat16(x);
    __nv_bfloat16 hy = __float2bfloat16(y);
    __nv_bfloat16 lx = __float2bfloat16(x - __bfloat162float(hx));
    __nv_bfloat16 ly = __float2bfloat16(y - __bfloat162float(hy));
    hi = ((uint32_t)__bfloat16_as_ushort(hy) << 16) | __bfloat16_as_ushort(hx);
    lo = ((uint32_t)__bfloat16_as_ushort(ly) << 16) | __bfloat16_as_ushort(lx);
}
__device__ __forceinline__ void ldm_x4(uint32_t* r, uint32_t addr) {
    asm volatile("ldmatrix.sync.aligned.m8n8.x4.shared.b16 {%0,%1,%2,%3}, [%4];"
        : "=r"(r[0]), "=r"(r[1]), "=r"(r[2]), "=r"(r[3]) : "r"(addr));
}
__device__ __forceinline__ void ldm_x4t(uint32_t* r, uint32_t addr) {
    asm volatile("ldmatrix.sync.aligned.m8n8.x4.trans.shared.b16 {%0,%1,%2,%3}, [%4];"
        : "=r"(r[0]), "=r"(r[1]), "=r"(r[2]), "=r"(r[3]) : "r"(addr));
}
__device__ __forceinline__ void mma16816(float* d, const uint32_t* a, const uint32_t* b) {
    asm volatile(
        "mma.sync.aligned.m16n8k16.row.col.f32.bf16.bf16.f32 "
        "{%0,%1,%2,%3}, {%4,%5,%6,%7}, {%8,%9}, {%0,%1,%2,%3};"
        : "+f"(d[0]), "+f"(d[1]), "+f"(d[2]), "+f"(d[3])
        : "r"(a[0]), "r"(a[1]), "r"(a[2]), "r"(a[3]), "r"(b[0]), "r"(b[1]));
}
#define CP16(dst, src) \
    asm volatile("cp.async.cg.shared.global [%0], [%1], 16;" :: "r"(dst), "l"(src))
#define CPCOMMIT() asm volatile("cp.async.commit_group;" ::: "memory")
#define CPWAIT1()  asm volatile("cp.async.wait_group 1;" ::: "memory")
#define CPWAIT0()  asm volatile("cp.async.wait_group 0;" ::: "memory")

// =======================================================================
// bf16-input split GEMM: C = A @ B^T; A=[M,K] (hi/lo), B=[N,K] (hi/lo)
// OSPLIT=0: fp32 C.  OSPLIT=1: split-bf16 Ch/Cl.
// 128x128 CTA tile, BK=32, 256 threads, cp.async double buffer.
// =======================================================================
#define GPITCH 40
#define TILE_BYTES (128 * GPITCH * 2)      // 10240
#define STAGE_BYTES (4 * TILE_BYTES)       // 40960
#define GEMM_SMEM (2 * STAGE_BYTES)        // 81920

template <int OSPLIT>
__global__ __launch_bounds__(256, 1) void mma_gemm_bf(
    const __nv_bfloat16* __restrict__ Ah, const __nv_bfloat16* __restrict__ Al,
    const __nv_bfloat16* __restrict__ Bh, const __nv_bfloat16* __restrict__ Bl,
    float* __restrict__ C, __nv_bfloat16* __restrict__ Ch, __nv_bfloat16* __restrict__ Cl,
    int M, int N, int K, long long sA, long long sB, long long sC)
{
    extern __shared__ char sm[];
    const uint32_t smb = smem_u32(sm);
    const int tid = threadIdx.x, wid = tid >> 5, lane = tid & 31;

    const size_t zo = (size_t)blockIdx.z;
    const __nv_bfloat16* Ahb = Ah + zo * sA;
    const __nv_bfloat16* Alb = Al + zo * sA;
    const __nv_bfloat16* Bhb = Bh + zo * sB;
    const __nv_bfloat16* Blb = Bl + zo * sB;
    const int m0 = blockIdx.x * 128, n0 = blockIdx.y * 128;

    const int warp_m = wid >> 2, warp_n = wid & 3;
    const int mbase = warp_m * 64, nbase = warp_n * 32;

    float acc[4][4][4];
#pragma unroll
    for (int i = 0; i < 4; i++)
#pragma unroll
        for (int j = 0; j < 4; j++)
#pragma unroll
            for (int q = 0; q < 4; q++) acc[i][j][q] = 0.f;

    const int nst = K >> 5;

    // cp.async one 32-K stage into buffer (s&1)
    const int c_tile = 0;  (void)c_tile;
    auto issue = [&](int s) {
        const int k0 = s << 5;
        const uint32_t sb = smb + (uint32_t)(s & 1) * STAGE_BYTES;
        const __nv_bfloat16* srcs[4] = {
            Ahb + (size_t)m0 * K + k0, Alb + (size_t)m0 * K + k0,
            Bhb + (size_t)n0 * K + k0, Blb + (size_t)n0 * K + k0 };
#pragma unroll
        for (int q = 0; q < 8; ++q) {
            const int c = q * 256 + tid;           // 0..2047
            const int tile = c >> 9, rem = c & 511;
            const int row = rem >> 2, c16 = rem & 3;
            const uint32_t dst = sb + tile * TILE_BYTES + row * (GPITCH * 2) + c16 * 16;
            const __nv_bfloat16* src = srcs[tile] + (size_t)row * K + c16 * 8;
            CP16(dst, src);
        }
    };

    issue(0); CPCOMMIT();

    const int a_row = lane & 15;
    const int a_kad = (lane >> 4) << 3;
    const int b_row = (lane & 7) + ((lane & 16) >> 1);
    const int b_kad = lane & 8;

    for (int s = 0; s < nst; ++s) {
        if (s + 1 < nst) { issue(s + 1); CPCOMMIT(); CPWAIT1(); }
        else             { CPWAIT0(); }
        __syncthreads();
        const uint32_t base = smb + (uint32_t)(s & 1) * STAGE_BYTES;
#pragma unroll
        for (int ks = 0; ks < 2; ++ks) {
            uint32_t ah[4][4], al[4][4], bh[4][2], bl[4][2];
            const int acol = (ks << 4) + a_kad;
            const int bcol = (ks << 4) + b_kad;
#pragma unroll
            for (int am = 0; am < 4; ++am) {
                const uint32_t off = (mbase + am * 16 + a_row) * (GPITCH * 2) + acol * 2;
                ldm_x4(ah[am], base + off);
                ldm_x4(al[am], base + TILE_BYTES + off);
            }
#pragma unroll
            for (int bg = 0; bg < 2; ++bg) {
                uint32_t r[4];
                const uint32_t off = (nbase + bg * 16 + b_row) * (GPITCH * 2) + bcol * 2;
                ldm_x4(r, base + 2 * TILE_BYTES + off);
                bh[bg * 2][0] = r[0]; bh[bg * 2][1] = r[1];
                bh[bg * 2 + 1][0] = r[2]; bh[bg * 2 + 1][1] = r[3];
                ldm_x4(r, base + 3 * TILE_BYTES + off);
                bl[bg * 2][0] = r[0]; bl[bg * 2][1] = r[1];
                bl[bg * 2 + 1][0] = r[2]; bl[bg * 2 + 1][1] = r[3];
            }
#pragma unroll
            for (int am = 0; am < 4; ++am)
#pragma unroll
                for (int bn = 0; bn < 4; ++bn) {
                    mma16816(acc[am][bn], ah[am], bh[bn]);
                    mma16816(acc[am][bn], ah[am], bl[bn]);
                    mma16816(acc[am][bn], al[am], bh[bn]);
                }
        }
        __syncthreads();
    }

    const int erow = lane >> 2, ecol = (lane & 3) << 1;
#pragma unroll
    for (int am = 0; am < 4; ++am) {
        const int r0 = m0 + mbase + am * 16 + erow;
#pragma unroll
        for (int bn = 0; bn < 4; ++bn) {
            const int c0 = n0 + nbase + bn * 8 + ecol;
            if (OSPLIT == 0) {
                float* Cb = C + zo * sC;
                *(float2*)&Cb[(size_t)r0 * N + c0] =
                    make_float2(acc[am][bn][0], acc[am][bn][1]);
                *(float2*)&Cb[(size_t)(r0 + 8) * N + c0] =
                    make_float2(acc[am][bn][2], acc[am][bn][3]);
            } else {
                __nv_bfloat16* Chb = Ch + zo * sC;
                __nv_bfloat16* Clb = Cl + zo * sC;
                uint32_t h01, l01, h23, l23;
                split2(acc[am][bn][0], acc[am][bn][1], h01, l01);
                split2(acc[am][bn][2], acc[am][bn][3], h23, l23);
                *(uint32_t*)&Chb[(size_t)r0 * N + c0]       = h01;
                *(uint32_t*)&Clb[(size_t)r0 * N + c0]       = l01;
                *(uint32_t*)&Chb[(size_t)(r0 + 8) * N + c0] = h23;
                *(uint32_t*)&Clb[(size_t)(r0 + 8) * N + c0] = l23;
            }
        }
    }
}

// ---------------- one-time split kernels ----------------
__global__ void split4_kernel(const float* __restrict__ src,
                              __nv_bfloat16* __restrict__ hi,
                              __nv_bfloat16* __restrict__ lo, int n4)
{
    const int i = blockIdx.x * 256 + threadIdx.x;
    if (i >= n4) return;
    float4 v = ((const float4*)src)[i];
    uint32_t h01, l01, h23, l23;
    split2(v.x, v.y, h01, l01);
    split2(v.z, v.w, h23, l23);
    ((uint2*)hi)[i] = make_uint2(h01, h23);
    ((uint2*)lo)[i] = make_uint2(l01, l23);
}

__global__ void concat_split_kernel(const float* __restrict__ a, const float* __restrict__ b,
                                    const float* __restrict__ c, const float* __restrict__ d)
{
    const int i4 = blockIdx.x * 256 + threadIdx.x;        // < 65536
    const int rt = i4 >> 14, rem = i4 & 16383;
    const float* src = (rt == 0) ? a : (rt == 1) ? b : (rt == 2) ? c : d;
    float4 v = ((const float4*)src)[rem];
    uint32_t h01, l01, h23, l23;
    split2(v.x, v.y, h01, l01);
    split2(v.z, v.w, h23, l23);
    ((uint2*)g_whi)[i4] = make_uint2(h01, h23);
    ((uint2*)g_wlo)[i4] = make_uint2(l01, l23);
}

// ---------------- router ----------------
__global__ void router_kernel(const float* __restrict__ importance)
{
    const int rt = blockIdx.x, b = blockIdx.y;
    const int k = (rt == 0) ? KC_ : KE_;
    __shared__ float wpart[8][64];
    __shared__ float w[64];
    const int tid = threadIdx.x, warp = tid >> 5, lane = tid & 31;

    float acc0 = 0.f, acc1 = 0.f;
    for (int s = warp; s < S_; s += 8) {
        const float* lp = g_logits + ((long long)(b * S_ + s)) * 256 + rt * 64;
        float v0 = lp[lane], v1 = lp[lane + 32];
        float mx = fmaxf(v0, v1);
#pragma unroll
        for (int off = 16; off; off >>= 1) mx = fmaxf(mx, __shfl_xor_sync(~0u, mx, off));
        float e0 = __expf(v0 - mx), e1 = __expf(v1 - mx);
        float smv = e0 + e1;
#pragma unroll
        for (int off = 16; off; off >>= 1) smv += __shfl_xor_sync(~0u, smv, off);
        float c = importance[b * S_ + s] / smv;
        acc0 += e0 * c;
        acc1 += e1 * c;
    }
    wpart[warp][lane]      = acc0;
    wpart[warp][lane + 32] = acc1;
    __syncthreads();
    if (tid < 64) {
        float t = 0.f;
#pragma unroll
        for (int wi = 0; wi < 8; wi++) t += wpart[wi][tid];
        w[tid] = t;
    }
    __syncthreads();
    if (tid == 0) {
        float tot = 0.f;
        for (int n = 0; n < 64; n++) tot += w[n];
        const float inv = 1.f / (tot + 1e-8f);
        float tw[16]; int ti[16]; bool used[64];
        for (int n = 0; n < 64; n++) used[n] = false;
        for (int kk = 0; kk < k; kk++) {
            float best = -1e30f; int bi = 0;
            for (int n = 0; n < 64; n++) {
                float v = w[n] * inv;
                if (!used[n] && v > best) { best = v; bi = n; }
            }
            used[bi] = true; tw[kk] = best; ti[kk] = bi;
        }
        float ts = 0.f;
        for (int kk = 0; kk < k; kk++) ts += tw[kk];
        const float inv2 = 1.f / (ts + 1e-8f);
        for (int kk = 0; kk < k; kk++) {
            g_tw[(rt * B_ + b) * 16 + kk] = tw[kk] * inv2;
            g_ti[(rt * B_ + b) * 16 + kk] = ti[kk];
        }
    }
}

// ---------------- mix compress -> split bf16 [b][r][d] -----
__global__ void mix_compressT_kernel(const float* __restrict__ cn)
{
    const int b = blockIdx.y;
    const int dt = blockIdx.x >> 3, rt = blockIdx.x & 7;
    const int d0 = dt * 32, r0 = rt * 32;
    __shared__ float cw[KC_]; __shared__ int ci[KC_];
    __shared__ float ts[32][33];
    if (threadIdx.x < KC_) {
        cw[threadIdx.x] = g_tw[(0 * B_ + b) * 16 + threadIdx.x];
        ci[threadIdx.x] = g_ti[(0 * B_ + b) * 16 + threadIdx.x];
    }
    __syncthreads();
    const int tid = threadIdx.x;
    const int dd = tid >> 3, rr = (tid & 7) << 2;
    float4 acc = {0.f, 0.f, 0.f, 0.f};
#pragma unroll
    for (int kk = 0; kk < KC_; kk++) {
        const float4 v = *(const float4*)(cn + ((size_t)ci[kk] * D_ + d0 + dd) * R_ + r0 + rr);
        const float wv = cw[kk];
        acc.x += wv * v.x; acc.y += wv * v.y; acc.z += wv * v.z; acc.w += wv * v.w;
    }
    ts[dd][rr] = acc.x; ts[dd][rr + 1] = acc.y; ts[dd][rr + 2] = acc.z; ts[dd][rr + 3] = acc.w;
    __syncthreads();
    const int rw = tid >> 3, dw = (tid & 7) << 2;
    float4 o = {ts[dw][rw], ts[dw + 1][rw], ts[dw + 2][rw], ts[dw + 3][rw]};
    uint32_t h01, l01, h23, l23;
    split2(o.x, o.y, h01, l01);
    split2(o.z, o.w, h23, l23);
    const size_t base = ((size_t)b * R_ + r0 + rw) * D_ + d0 + dw;
    *(uint2*)&g_schi[base] = make_uint2(h01, h23);
    *(uint2*)&g_sclo[base] = make_uint2(l01, l23);
}

// ---------------- mix expand -> split bf16 [b][3D][r] --
__global__ void mix_expandT_kernel(const float* __restrict__ pool)
{
    const int which = blockIdx.y, b = blockIdx.z;
    const int dt = blockIdx.x >> 3, rt = blockIdx.x & 7;
    const int d0 = dt * 32, r0 = rt * 32;
    const int rtr = which + 1;
    __shared__ float ew[KE_]; __shared__ int ei[KE_];
    __shared__ float ts[32][33];
    if (threadIdx.x < KE_) {
        ew[threadIdx.x] = g_tw[(rtr * B_ + b) * 16 + threadIdx.x];
        ei[threadIdx.x] = g_ti[(rtr * B_ + b) * 16 + threadIdx.x];
    }
    __syncthreads();
    const int tid = threadIdx.x;
    const int rr = tid >> 3, dd = (tid & 7) << 2;
    float4 acc = {0.f, 0.f, 0.f, 0.f};
#pragma unroll
    for (int kk = 0; kk < KE_; kk++) {
        const float4 v = *(const float4*)(pool + ((size_t)ei[kk] * R_ + r0 + rr) * D_ + d0 + dd);
        const float wv = ew[kk];
        acc.x += wv * v.x; acc.y += wv * v.y; acc.z += wv * v.z; acc.w += wv * v.w;
    }
    ts[rr][dd] = acc.x; ts[rr][dd + 1] = acc.y; ts[rr][dd + 2] = acc.z; ts[rr][dd + 3] = acc.w;
    __syncthreads();
    const int dw = tid >> 3, rw = (tid & 7) << 2;
    float4 o = {ts[rw][dw], ts[rw + 1][dw], ts[rw + 2][dw], ts[rw + 3][dw]};
    uint32_t h01, l01, h23, l23;
    split2(o.x, o.y, h01, l01);
    split2(o.z, o.w, h23, l23);
    const size_t base = ((size_t)b * 3 * D_ + (size_t)which * D_ + d0 + dw) * R_ + r0 + rw;
    *(uint2*)&g_ehi[base] = make_uint2(h01, h23);
    *(uint2*)&g_elo[base] = make_uint2(l01, l23);
}

// =======================================================================
// flash attention (mma, bf16 inputs via cp.async)
// =======================================================================
#define FP 72
#define FQHI 0
#define FQLO (128 * FP)
#define FKHI (256 * FP)
#define FKLO (FKHI + 64 * FP)
#define FVHI (FKLO + 64 * FP)
#define FVLO (FVHI + 64 * FP)
#define FLASH_SMEM ((FVLO + 64 * FP) * 2)
#define SC2L 0.18033688011112042f

__global__ __launch_bounds__(256, 1) void flash_mma_bf(
    const __nv_bfloat16* __restrict__ qh, const __nv_bfloat16* __restrict__ ql,
    __nv_bfloat16* __restrict__ oh, __nv_bfloat16* __restrict__ ol)
{
    extern __shared__ char smc[];
    const uint32_t smb = smem_u32(smc);
    const int tid = threadIdx.x, w = tid >> 5, lane = tid & 31;
    const int b = blockIdx.y >> 4, h = blockIdx.y & 15;
    const int q0 = blockIdx.x * 128;
    const size_t bbase = (size_t)b * S_ * (3 * D_) + h * DH_;

    // ---- Q tiles via cp.async (joins first k-tile commit group) ----
#pragma unroll
    for (int q = 0; q < 8; ++q) {
        const int c = q * 256 + tid;               // 0..2047
        const int arr = c >> 10, rem = c & 1023;
        const int row = rem >> 3, c16 = rem & 7;
        const uint32_t dst = smb + (arr ? FQLO : FQHI) * 2 + row * (FP * 2) + c16 * 16;
        const __nv_bfloat16* src = (arr ? ql : qh) + bbase
                                   + (size_t)(q0 + row) * (3 * D_) + c16 * 8;
        CP16(dst, src);
    }

    float sacc[8][4], oacc[8][4];
    float m0v = -1e30f, m1v = -1e30f, l0v = 0.f, l1v = 0.f;
#pragma unroll
    for (int t = 0; t < 8; t++)
#pragma unroll
        for (int e = 0; e < 4; e++) oacc[t][e] = 0.f;

    const int a_row = lane & 15;
    const int a_kad = (lane >> 4) << 3;
    const int b_row = (lane & 7) + ((lane & 16) >> 1);
    const int b_kad = lane & 8;
    const int qwarp = q0 + w * 16;
    const int r0 = lane >> 2;
    const int c0l = (lane & 3) << 1;

    const int kend = q0 + 128;
    for (int k0 = 0; k0 < kend; k0 += 64) {
        __syncthreads();
        // ---- K,V tiles via cp.async ----
#pragma unroll
        for (int q = 0; q < 8; ++q) {
            const int c = q * 256 + tid;           // 0..2047
            const int tile = c >> 9, rem = c & 511;
            const int row = rem >> 3, c16 = rem & 7;
            static const int dsts[4] = {FKHI, FKLO, FVHI, FVLO};
            const uint32_t dst = smb + dsts[tile] * 2 + row * (FP * 2) + c16 * 16;
            const __nv_bfloat16* sp = (tile & 1) ? ql : qh;
            const size_t goff = bbase + ((tile >> 1) ? 2 * D_ : D_)
                                + (size_t)(k0 + row) * (3 * D_) + c16 * 8;
            CP16(dst, sp + goff);
        }
        CPCOMMIT(); CPWAIT0();
        __syncthreads();

        if (k0 > qwarp + 15) continue;

        // ---- S = Q K^T (3-term split) ----
#pragma unroll
        for (int t = 0; t < 8; t++)
#pragma unroll
            for (int e = 0; e < 4; e++) sacc[t][e] = 0.f;
#pragma unroll
        for (int kk = 0; kk < 4; ++kk) {
            uint32_t qhf[4], qlf[4];
            const uint32_t qoff = 2 * (uint32_t)((w * 16 + a_row) * FP + kk * 16 + a_kad);
            ldm_x4(qhf, smb + 2 * FQHI + qoff);
            ldm_x4(qlf, smb + 2 * FQLO + qoff);
#pragma unroll
            for (int jt = 0; jt < 4; ++jt) {
                uint32_t khf[4], klf[4];
                const uint32_t koff = 2 * (uint32_t)((jt * 16 + b_row) * FP + kk * 16 + b_kad);
                ldm_x4(khf, smb + 2 * FKHI + koff);
                ldm_x4(klf, smb + 2 * FKLO + koff);
                mma16816(sacc[jt * 2],     qhf, khf);
                mma16816(sacc[jt * 2 + 1], qhf, khf + 2);
                mma16816(sacc[jt * 2],     qhf, klf);
                mma16816(sacc[jt * 2 + 1], qhf, klf + 2);
                mma16816(sacc[jt * 2],     qlf, khf);
                mma16816(sacc[jt * 2 + 1], qlf, khf + 2);
            }
        }

        if (k0 + 63 > qwarp) {
#pragma unroll
            for (int t = 0; t < 8; t++) {
                const int kg = k0 + t * 8 + c0l;
#pragma unroll
                for (int e = 0; e < 4; e++) {
                    const int kge = kg + (e & 1);
                    const int qg = qwarp + r0 + ((e >> 1) << 3);
                    if (kge > qg) sacc[t][e] = -1e30f;
                }
            }
        }

        float mx0 = -1e30f, mx1 = -1e30f;
#pragma unroll
        for (int t = 0; t < 8; t++) {
            mx0 = fmaxf(mx0, fmaxf(sacc[t][0], sacc[t][1]));
            mx1 = fmaxf(mx1, fmaxf(sacc[t][2], sacc[t][3]));
        }
        mx0 = fmaxf(mx0, __shfl_xor_sync(~0u, mx0, 1));
        mx0 = fmaxf(mx0, __shfl_xor_sync(~0u, mx0, 2));
        mx1 = fmaxf(mx1, __shfl_xor_sync(~0u, mx1, 1));
        mx1 = fmaxf(mx1, __shfl_xor_sync(~0u, mx1, 2));
        const float mn0 = fmaxf(m0v, mx0), mn1 = fmaxf(m1v, mx1);
        const float al0 = exp2f((m0v - mn0) * SC2L);
        const float al1 = exp2f((m1v - mn1) * SC2L);
        float sum0 = 0.f, sum1 = 0.f;
        uint32_t ph[8][2], pl[8][2];
#pragma unroll
        for (int t = 0; t < 8; t++) {
            float p0 = exp2f((sacc[t][0] - mn0) * SC2L);
            float p1 = exp2f((sacc[t][1] - mn0) * SC2L);
            float p2 = exp2f((sacc[t][2] - mn1) * SC2L);
            float p3 = exp2f((sacc[t][3] - mn1) * SC2L);
            sum0 += p0 + p1; sum1 += p2 + p3;
            split2(p0, p1, ph[t][0], pl[t][0]);
            split2(p2, p3, ph[t][1], pl[t][1]);
        }
        sum0 += __shfl_xor_sync(~0u, sum0, 1);
        sum0 += __shfl_xor_sync(~0u, sum0, 2);
        sum1 += __shfl_xor_sync(~0u, sum1, 1);
        sum1 += __shfl_xor_sync(~0u, sum1, 2);
        l0v = l0v * al0 + sum0;
        l1v = l1v * al1 + sum1;
        m0v = mn0; m1v = mn1;
#pragma unroll
        for (int t = 0; t < 8; t++) {
            oacc[t][0] *= al0; oacc[t][1] *= al0;
            oacc[t][2] *= al1; oacc[t][3] *= al1;
        }

#pragma unroll
        for (int g = 0; g < 4; ++g) {
            uint32_t Ahf[4] = {ph[2 * g][0], ph[2 * g][1], ph[2 * g + 1][0], ph[2 * g + 1][1]};
            uint32_t Alf[4] = {pl[2 * g][0], pl[2 * g][1], pl[2 * g + 1][0], pl[2 * g + 1][1]};
#pragma unroll
            for (int dp = 0; dp < 4; ++dp) {
                uint32_t vhf[4], vlf[4];
                const uint32_t voff = 2 * (uint32_t)((g * 16 + (lane & 15)) * FP
                                                     + dp * 16 + ((lane >> 4) << 3));
                ldm_x4t(vhf, smb + 2 * FVHI + voff);
                ldm_x4t(vlf, smb + 2 * FVLO + voff);
                mma16816(oacc[dp * 2],     Ahf, vhf);
                mma16816(oacc[dp * 2 + 1], Ahf, vhf + 2);
                mma16816(oacc[dp * 2],     Alf, vhf);
                mma16816(oacc[dp * 2 + 1], Alf, vhf + 2);
                mma16816(oacc[dp * 2],     Ahf, vlf);
                mma16816(oacc[dp * 2 + 1], Ahf, vlf + 2);
            }
        }
    }

    // ---- write split output ----
    const float inv0 = 1.f / l0v, inv1 = 1.f / l1v;
    __nv_bfloat16* ohp = oh + (size_t)b * S_ * D_ + (size_t)h * DH_;
    __nv_bfloat16* olp = ol + (size_t)b * S_ * D_ + (size_t)h * DH_;
    const int row0 = q0 + w * 16 + r0;
#pragma unroll
    for (int t = 0; t < 8; t++) {
        const int c = t * 8 + c0l;
        uint32_t h01, l01, h23, l23;
        split2(oacc[t][0] * inv0, oacc[t][1] * inv0, h01, l01);
        split2(oacc[t][2] * inv1, oacc[t][3] * inv1, h23, l23);
        *(uint32_t*)&ohp[(size_t)row0 * D_ + c]       = h01;
        *(uint32_t*)&olp[(size_t)row0 * D_ + c]       = l01;
        *(uint32_t*)&ohp[(size_t)(row0 + 8) * D_ + c] = h23;
        *(uint32_t*)&olp[(size_t)(row0 + 8) * D_ + c] = l23;
    }
}

// ---------------- launch ----------------
extern "C" void kernel_launch(void* const* d_in, const int* in_sizes, int n_in,
                              void* d_out, int out_size)
{
    const float* x    = (const float*)d_in[0];
    const float* imp  = (const float*)d_in[1];
    const float* Wc   = (const float*)d_in[2];
    const float* Wq   = (const float*)d_in[3];
    const float* Wk   = (const float*)d_in[4];
    const float* Wv   = (const float*)d_in[5];
    const float* cn   = (const float*)d_in[6];
    const float* pool = (const float*)d_in[7];
    const float* WO   = (const float*)d_in[8];
    float* out = (float*)d_out;

    float* pLog;
    __nv_bfloat16 *pxh, *pxl, *pwh, *pwl, *psh, *psl, *phh, *phl;
    __nv_bfloat16 *peh, *pel, *pqh, *pql, *pah, *pal, *poh2, *pol2;
    cudaGetSymbolAddress((void**)&pLog, g_logits);
    cudaGetSymbolAddress((void**)&pxh, g_xhi);  cudaGetSymbolAddress((void**)&pxl, g_xlo);
    cudaGetSymbolAddress((void**)&pwh, g_whi);  cudaGetSymbolAddress((void**)&pwl, g_wlo);
    cudaGetSymbolAddress((void**)&psh, g_schi); cudaGetSymbolAddress((void**)&psl, g_sclo);
    cudaGetSymbolAddress((void**)&phh, g_hhi);  cudaGetSymbolAddress((void**)&phl, g_hlo);
    cudaGetSymbolAddress((void**)&peh, g_ehi);  cudaGetSymbolAddress((void**)&pel, g_elo);
    cudaGetSymbolAddress((void**)&pqh, g_qhi);  cudaGetSymbolAddress((void**)&pql, g_qlo);
    cudaGetSymbolAddress((void**)&pah, g_aohi); cudaGetSymbolAddress((void**)&pal, g_aolo);
    cudaGetSymbolAddress((void**)&poh2, g_wohi); cudaGetSymbolAddress((void**)&pol2, g_wolo);

    cudaFuncSetAttribute(mma_gemm_bf<0>, cudaFuncAttributeMaxDynamicSharedMemorySize, GEMM_SMEM);
    cudaFuncSetAttribute(mma_gemm_bf<1>, cudaFuncAttributeMaxDynamicSharedMemorySize, GEMM_SMEM);
    cudaFuncSetAttribute(flash_mma_bf, cudaFuncAttributeMaxDynamicSharedMemorySize, FLASH_SMEM);

    // one-time splits
    split4_kernel<<<8192, 256>>>(x, pxh, pxl, B_ * S_ * D_ / 4);
    concat_split_kernel<<<256, 256>>>(Wc, Wq, Wk, Wv);
    split4_kernel<<<1024, 256>>>(WO, poh2, pol2, D_ * D_ / 4);

    // logits = x @ Wall^T
    mma_gemm_bf<0><<<dim3(64, 2, 1), 256, GEMM_SMEM>>>(
        pxh, pxl, pwh, pwl, pLog, nullptr, nullptr, 8192, 256, 1024, 0, 0, 0);
    router_kernel<<<dim3(4, 8), 256>>>(imp);
    mix_compressT_kernel<<<dim3(256, 8), 256>>>(cn);
    // h = x @ sharedc^T  -> split bf16
    mma_gemm_bf<1><<<dim3(8, 2, 8), 256, GEMM_SMEM>>>(
        pxh, pxl, psh, psl, nullptr, phh, phl, 1024, 256, 1024,
        (long long)S_ * D_, (long long)R_ * D_, (long long)S_ * R_);
    mix_expandT_kernel<<<dim3(256, 3, 8), 256>>>(pool);
    // qkv = h @ eAll^T  -> split bf16
    mma_gemm_bf<1><<<dim3(8, 24, 8), 256, GEMM_SMEM>>>(
        phh, phl, peh, pel, nullptr, pqh, pql, 1024, 3 * D_, 256,
        (long long)S_ * R_, (long long)3 * D_ * R_, (long long)S_ * 3 * D_);
    // flash attention -> split bf16 aout
    flash_mma_bf<<<dim3(8, 128), 256, FLASH_SMEM>>>(pqh, pql, pah, pal);
    // out = aout @ W_O^T  (fp32)
    mma_gemm_bf<0><<<dim3(64, 8, 1), 256, GEMM_SMEM>>>(
        pah, pal, poh2, pol2, out, nullptr, nullptr, 8192, 1024, 1024, 0, 0, 0);
}

// round 6
// speedup vs baseline: 2.4447x; 1.0855x over previous
#include <cuda_runtime.h>
#include <cuda_bf16.h>
#include <cstdint>

// ---------------- problem constants ----------------
#define B_  8
#define S_  1024
#define D_  1024
#define H_  16
#define DH_ 64
#define R_  256
#define KC_ 16
#define KE_ 8

// ---------------- scratch (device globals) ----------
__device__ float g_logits[B_ * S_ * 256];
__device__ float g_tw[4 * B_ * 16];
__device__ int   g_ti[4 * B_ * 16];
__device__ __nv_bfloat16 g_xhi[B_ * S_ * D_],  g_xlo[B_ * S_ * D_];
__device__ __nv_bfloat16 g_whi[256 * D_],      g_wlo[256 * D_];
__device__ __nv_bfloat16 g_schi[B_ * R_ * D_], g_sclo[B_ * R_ * D_];     // [b][r][d]
__device__ __nv_bfloat16 g_hhi[B_ * S_ * R_],  g_hlo[B_ * S_ * R_];      // [b][s][r]
__device__ __nv_bfloat16 g_ehi[B_ * 3 * D_ * R_], g_elo[B_ * 3 * D_ * R_]; // [b][3D][r]
__device__ __nv_bfloat16 g_qhi[B_ * S_ * 3 * D_], g_qlo[B_ * S_ * 3 * D_]; // [b][s][3D]
__device__ __nv_bfloat16 g_aohi[B_ * S_ * D_], g_aolo[B_ * S_ * D_];     // [b][s][D]
__device__ __nv_bfloat16 g_wohi[D_ * D_],      g_wolo[D_ * D_];

// ---------------- helpers ----------------
__device__ __forceinline__ uint32_t smem_u32(const void* p) {
    uint32_t a;
    asm("{ .reg .u64 t; cvta.to.shared.u64 t, %1; cvt.u32.u64 %0, t; }"
        : "=r"(a) : "l"(p));
    return a;
}
__device__ __forceinline__ void split2(float x, float y, uint32_t& hi, uint32_t& lo) {
    __nv_bfloat16 hx = __float2bfloat16(x);
    __nv_bfloat16 hy = __float2bfloat16(y);
    __nv_bfloat16 lx = __float2bfloat16(x - __bfloat162float(hx));
    __nv_bfloat16 ly = __float2bfloat16(y - __bfloat162float(hy));
    hi = ((uint32_t)__bfloat16_as_ushort(hy) << 16) | __bfloat16_as_ushort(hx);
    lo = ((uint32_t)__bfloat16_as_ushort(ly) << 16) | __bfloat16_as_ushort(lx);
}
__device__ __forceinline__ void ldm_x4(uint32_t* r, uint32_t addr) {
    asm volatile("ldmatrix.sync.aligned.m8n8.x4.shared.b16 {%0,%1,%2,%3}, [%4];"
        : "=r"(r[0]), "=r"(r[1]), "=r"(r[2]), "=r"(r[3]) : "r"(addr));
}
__device__ __forceinline__ void ldm_x4t(uint32_t* r, uint32_t addr) {
    asm volatile("ldmatrix.sync.aligned.m8n8.x4.trans.shared.b16 {%0,%1,%2,%3}, [%4];"
        : "=r"(r[0]), "=r"(r[1]), "=r"(r[2]), "=r"(r[3]) : "r"(addr));
}
__device__ __forceinline__ void mma16816(float* d, const uint32_t* a, const uint32_t* b) {
    asm volatile(
        "mma.sync.aligned.m16n8k16.row.col.f32.bf16.bf16.f32 "
        "{%0,%1,%2,%3}, {%4,%5,%6,%7}, {%8,%9}, {%0,%1,%2,%3};"
        : "+f"(d[0]), "+f"(d[1]), "+f"(d[2]), "+f"(d[3])
        : "r"(a[0]), "r"(a[1]), "r"(a[2]), "r"(a[3]), "r"(b[0]), "r"(b[1]));
}
#define CP16(dst, src) \
    asm volatile("cp.async.cg.shared.global [%0], [%1], 16;" :: "r"(dst), "l"(src))
#define CPCOMMIT() asm volatile("cp.async.commit_group;" ::: "memory")
#define CPWAIT1()  asm volatile("cp.async.wait_group 1;" ::: "memory")
#define CPWAIT0()  asm volatile("cp.async.wait_group 0;" ::: "memory")

// =======================================================================
// bf16-input split GEMM: C = A @ B^T; A=[M,K] (hi/lo), B=[N,K] (hi/lo)
// OSPLIT=0: fp32 C.  OSPLIT=1: split-bf16 Ch/Cl.
// 128x128 CTA tile, BK=32, 256 threads, cp.async double buffer, 2 CTA/SM.
// =======================================================================
#define GPITCH 40
#define TILE_BYTES (128 * GPITCH * 2)      // 10240
#define STAGE_BYTES (4 * TILE_BYTES)       // 40960
#define GEMM_SMEM (2 * STAGE_BYTES)        // 81920

template <int OSPLIT>
__global__ __launch_bounds__(256, 2) void mma_gemm_bf(
    const __nv_bfloat16* __restrict__ Ah, const __nv_bfloat16* __restrict__ Al,
    const __nv_bfloat16* __restrict__ Bh, const __nv_bfloat16* __restrict__ Bl,
    float* __restrict__ C, __nv_bfloat16* __restrict__ Ch, __nv_bfloat16* __restrict__ Cl,
    int M, int N, int K, long long sA, long long sB, long long sC)
{
    extern __shared__ char sm[];
    const uint32_t smb = smem_u32(sm);
    const int tid = threadIdx.x, wid = tid >> 5, lane = tid & 31;

    const size_t zo = (size_t)blockIdx.z;
    const __nv_bfloat16* Ahb = Ah + zo * sA;
    const __nv_bfloat16* Alb = Al + zo * sA;
    const __nv_bfloat16* Bhb = Bh + zo * sB;
    const __nv_bfloat16* Blb = Bl + zo * sB;
    const int m0 = blockIdx.x * 128, n0 = blockIdx.y * 128;

    const int warp_m = wid >> 2, warp_n = wid & 3;
    const int mbase = warp_m * 64, nbase = warp_n * 32;

    float acc[4][4][4];
#pragma unroll
    for (int i = 0; i < 4; i++)
#pragma unroll
        for (int j = 0; j < 4; j++)
#pragma unroll
            for (int q = 0; q < 4; q++) acc[i][j][q] = 0.f;

    const int nst = K >> 5;

    auto issue = [&](int s) {
        const int k0 = s << 5;
        const uint32_t sb = smb + (uint32_t)(s & 1) * STAGE_BYTES;
        const __nv_bfloat16* srcs[4] = {
            Ahb + (size_t)m0 * K + k0, Alb + (size_t)m0 * K + k0,
            Bhb + (size_t)n0 * K + k0, Blb + (size_t)n0 * K + k0 };
#pragma unroll
        for (int q = 0; q < 8; ++q) {
            const int c = q * 256 + tid;           // 0..2047
            const int tile = c >> 9, rem = c & 511;
            const int row = rem >> 2, c16 = rem & 3;
            const uint32_t dst = sb + tile * TILE_BYTES + row * (GPITCH * 2) + c16 * 16;
            const __nv_bfloat16* src = srcs[tile] + (size_t)row * K + c16 * 8;
            CP16(dst, src);
        }
    };

    issue(0); CPCOMMIT();

    const int a_row = lane & 15;
    const int a_kad = (lane >> 4) << 3;
    const int b_row = (lane & 7) + ((lane & 16) >> 1);
    const int b_kad = lane & 8;

    for (int s = 0; s < nst; ++s) {
        if (s + 1 < nst) { issue(s + 1); CPCOMMIT(); CPWAIT1(); }
        else             { CPWAIT0(); }
        __syncthreads();
        const uint32_t base = smb + (uint32_t)(s & 1) * STAGE_BYTES;
#pragma unroll
        for (int ks = 0; ks < 2; ++ks) {
            uint32_t ah[4][4], al[4][4], bh[4][2], bl[4][2];
            const int acol = (ks << 4) + a_kad;
            const int bcol = (ks << 4) + b_kad;
#pragma unroll
            for (int am = 0; am < 4; ++am) {
                const uint32_t off = (mbase + am * 16 + a_row) * (GPITCH * 2) + acol * 2;
                ldm_x4(ah[am], base + off);
                ldm_x4(al[am], base + TILE_BYTES + off);
            }
#pragma unroll
            for (int bg = 0; bg < 2; ++bg) {
                uint32_t r[4];
                const uint32_t off = (nbase + bg * 16 + b_row) * (GPITCH * 2) + bcol * 2;
                ldm_x4(r, base + 2 * TILE_BYTES + off);
                bh[bg * 2][0] = r[0]; bh[bg * 2][1] = r[1];
                bh[bg * 2 + 1][0] = r[2]; bh[bg * 2 + 1][1] = r[3];
                ldm_x4(r, base + 3 * TILE_BYTES + off);
                bl[bg * 2][0] = r[0]; bl[bg * 2][1] = r[1];
                bl[bg * 2 + 1][0] = r[2]; bl[bg * 2 + 1][1] = r[3];
            }
#pragma unroll
            for (int am = 0; am < 4; ++am)
#pragma unroll
                for (int bn = 0; bn < 4; ++bn) {
                    mma16816(acc[am][bn], ah[am], bh[bn]);
                    mma16816(acc[am][bn], ah[am], bl[bn]);
                    mma16816(acc[am][bn], al[am], bh[bn]);
                }
        }
        __syncthreads();
    }

    const int erow = lane >> 2, ecol = (lane & 3) << 1;
#pragma unroll
    for (int am = 0; am < 4; ++am) {
        const int r0 = m0 + mbase + am * 16 + erow;
#pragma unroll
        for (int bn = 0; bn < 4; ++bn) {
            const int c0 = n0 + nbase + bn * 8 + ecol;
            if (OSPLIT == 0) {
                float* Cb = C + zo * sC;
                *(float2*)&Cb[(size_t)r0 * N + c0] =
                    make_float2(acc[am][bn][0], acc[am][bn][1]);
                *(float2*)&Cb[(size_t)(r0 + 8) * N + c0] =
                    make_float2(acc[am][bn][2], acc[am][bn][3]);
            } else {
                __nv_bfloat16* Chb = Ch + zo * sC;
                __nv_bfloat16* Clb = Cl + zo * sC;
                uint32_t h01, l01, h23, l23;
                split2(acc[am][bn][0], acc[am][bn][1], h01, l01);
                split2(acc[am][bn][2], acc[am][bn][3], h23, l23);
                *(uint32_t*)&Chb[(size_t)r0 * N + c0]       = h01;
                *(uint32_t*)&Clb[(size_t)r0 * N + c0]       = l01;
                *(uint32_t*)&Chb[(size_t)(r0 + 8) * N + c0] = h23;
                *(uint32_t*)&Clb[(size_t)(r0 + 8) * N + c0] = l23;
            }
        }
    }
}

// ---------------- one-time split kernels ----------------
__global__ void split4_kernel(const float* __restrict__ src,
                              __nv_bfloat16* __restrict__ hi,
                              __nv_bfloat16* __restrict__ lo, int n4)
{
    const int i = blockIdx.x * 256 + threadIdx.x;
    if (i >= n4) return;
    float4 v = ((const float4*)src)[i];
    uint32_t h01, l01, h23, l23;
    split2(v.x, v.y, h01, l01);
    split2(v.z, v.w, h23, l23);
    ((uint2*)hi)[i] = make_uint2(h01, h23);
    ((uint2*)lo)[i] = make_uint2(l01, l23);
}

__global__ void concat_split_kernel(const float* __restrict__ a, const float* __restrict__ b,
                                    const float* __restrict__ c, const float* __restrict__ d)
{
    const int i4 = blockIdx.x * 256 + threadIdx.x;        // < 65536
    const int rt = i4 >> 14, rem = i4 & 16383;
    const float* src = (rt == 0) ? a : (rt == 1) ? b : (rt == 2) ? c : d;
    float4 v = ((const float4*)src)[rem];
    uint32_t h01, l01, h23, l23;
    split2(v.x, v.y, h01, l01);
    split2(v.z, v.w, h23, l23);
    ((uint2*)g_whi)[i4] = make_uint2(h01, h23);
    ((uint2*)g_wlo)[i4] = make_uint2(l01, l23);
}

// ---------------- router ----------------
__global__ void router_kernel(const float* __restrict__ importance)
{
    const int rt = blockIdx.x, b = blockIdx.y;
    const int k = (rt == 0) ? KC_ : KE_;
    __shared__ float wpart[8][64];
    __shared__ float w[64];
    const int tid = threadIdx.x, warp = tid >> 5, lane = tid & 31;

    float acc0 = 0.f, acc1 = 0.f;
    for (int s = warp; s < S_; s += 8) {
        const float* lp = g_logits + ((long long)(b * S_ + s)) * 256 + rt * 64;
        float v0 = lp[lane], v1 = lp[lane + 32];
        float mx = fmaxf(v0, v1);
#pragma unroll
        for (int off = 16; off; off >>= 1) mx = fmaxf(mx, __shfl_xor_sync(~0u, mx, off));
        float e0 = __expf(v0 - mx), e1 = __expf(v1 - mx);
        float smv = e0 + e1;
#pragma unroll
        for (int off = 16; off; off >>= 1) smv += __shfl_xor_sync(~0u, smv, off);
        float c = importance[b * S_ + s] / smv;
        acc0 += e0 * c;
        acc1 += e1 * c;
    }
    wpart[warp][lane]      = acc0;
    wpart[warp][lane + 32] = acc1;
    __syncthreads();
    if (tid < 64) {
        float t = 0.f;
#pragma unroll
        for (int wi = 0; wi < 8; wi++) t += wpart[wi][tid];
        w[tid] = t;
    }
    __syncthreads();
    if (tid == 0) {
        float tot = 0.f;
        for (int n = 0; n < 64; n++) tot += w[n];
        const float inv = 1.f / (tot + 1e-8f);
        float tw[16]; int ti[16]; bool used[64];
        for (int n = 0; n < 64; n++) used[n] = false;
        for (int kk = 0; kk < k; kk++) {
            float best = -1e30f; int bi = 0;
            for (int n = 0; n < 64; n++) {
                float v = w[n] * inv;
                if (!used[n] && v > best) { best = v; bi = n; }
            }
            used[bi] = true; tw[kk] = best; ti[kk] = bi;
        }
        float ts = 0.f;
        for (int kk = 0; kk < k; kk++) ts += tw[kk];
        const float inv2 = 1.f / (ts + 1e-8f);
        for (int kk = 0; kk < k; kk++) {
            g_tw[(rt * B_ + b) * 16 + kk] = tw[kk] * inv2;
            g_ti[(rt * B_ + b) * 16 + kk] = ti[kk];
        }
    }
}

// ---------------- mix compress -> split bf16 [b][r][d] -----
__global__ void mix_compressT_kernel(const float* __restrict__ cn)
{
    const int b = blockIdx.y;
    const int dt = blockIdx.x >> 3, rt = blockIdx.x & 7;
    const int d0 = dt * 32, r0 = rt * 32;
    __shared__ float cw[KC_]; __shared__ int ci[KC_];
    __shared__ float ts[32][33];
    if (threadIdx.x < KC_) {
        cw[threadIdx.x] = g_tw[(0 * B_ + b) * 16 + threadIdx.x];
        ci[threadIdx.x] = g_ti[(0 * B_ + b) * 16 + threadIdx.x];
    }
    __syncthreads();
    const int tid = threadIdx.x;
    const int dd = tid >> 3, rr = (tid & 7) << 2;
    float4 acc = {0.f, 0.f, 0.f, 0.f};
#pragma unroll
    for (int kk = 0; kk < KC_; kk++) {
        const float4 v = *(const float4*)(cn + ((size_t)ci[kk] * D_ + d0 + dd) * R_ + r0 + rr);
        const float wv = cw[kk];
        acc.x += wv * v.x; acc.y += wv * v.y; acc.z += wv * v.z; acc.w += wv * v.w;
    }
    ts[dd][rr] = acc.x; ts[dd][rr + 1] = acc.y; ts[dd][rr + 2] = acc.z; ts[dd][rr + 3] = acc.w;
    __syncthreads();
    const int rw = tid >> 3, dw = (tid & 7) << 2;
    float4 o = {ts[dw][rw], ts[dw + 1][rw], ts[dw + 2][rw], ts[dw + 3][rw]};
    uint32_t h01, l01, h23, l23;
    split2(o.x, o.y, h01, l01);
    split2(o.z, o.w, h23, l23);
    const size_t base = ((size_t)b * R_ + r0 + rw) * D_ + d0 + dw;
    *(uint2*)&g_schi[base] = make_uint2(h01, h23);
    *(uint2*)&g_sclo[base] = make_uint2(l01, l23);
}

// ---------------- mix expand -> split bf16 [b][3D][r] --
__global__ void mix_expandT_kernel(const float* __restrict__ pool)
{
    const int which = blockIdx.y, b = blockIdx.z;
    const int dt = blockIdx.x >> 3, rt = blockIdx.x & 7;
    const int d0 = dt * 32, r0 = rt * 32;
    const int rtr = which + 1;
    __shared__ float ew[KE_]; __shared__ int ei[KE_];
    __shared__ float ts[32][33];
    if (threadIdx.x < KE_) {
        ew[threadIdx.x] = g_tw[(rtr * B_ + b) * 16 + threadIdx.x];
        ei[threadIdx.x] = g_ti[(rtr * B_ + b) * 16 + threadIdx.x];
    }
    __syncthreads();
    const int tid = threadIdx.x;
    const int rr = tid >> 3, dd = (tid & 7) << 2;
    float4 acc = {0.f, 0.f, 0.f, 0.f};
#pragma unroll
    for (int kk = 0; kk < KE_; kk++) {
        const float4 v = *(const float4*)(pool + ((size_t)ei[kk] * R_ + r0 + rr) * D_ + d0 + dd);
        const float wv = ew[kk];
        acc.x += wv * v.x; acc.y += wv * v.y; acc.z += wv * v.z; acc.w += wv * v.w;
    }
    ts[rr][dd] = acc.x; ts[rr][dd + 1] = acc.y; ts[rr][dd + 2] = acc.z; ts[rr][dd + 3] = acc.w;
    __syncthreads();
    const int dw = tid >> 3, rw = (tid & 7) << 2;
    float4 o = {ts[rw][dw], ts[rw + 1][dw], ts[rw + 2][dw], ts[rw + 3][dw]};
    uint32_t h01, l01, h23, l23;
    split2(o.x, o.y, h01, l01);
    split2(o.z, o.w, h23, l23);
    const size_t base = ((size_t)b * 3 * D_ + (size_t)which * D_ + d0 + dw) * R_ + r0 + rw;
    *(uint2*)&g_ehi[base] = make_uint2(h01, h23);
    *(uint2*)&g_elo[base] = make_uint2(l01, l23);
}

// =======================================================================
// flash attention (mma, bf16 inputs via cp.async), 2 CTA/SM
// =======================================================================
#define FP 72
#define FQHI 0
#define FQLO (128 * FP)
#define FKHI (256 * FP)
#define FKLO (FKHI + 64 * FP)
#define FVHI (FKLO + 64 * FP)
#define FVLO (FVHI + 64 * FP)
#define FLASH_SMEM ((FVLO + 64 * FP) * 2)
#define SC2L 0.18033688011112042f

__global__ __launch_bounds__(256, 2) void flash_mma_bf(
    const __nv_bfloat16* __restrict__ qh, const __nv_bfloat16* __restrict__ ql,
    __nv_bfloat16* __restrict__ oh, __nv_bfloat16* __restrict__ ol)
{
    extern __shared__ char smc[];
    const uint32_t smb = smem_u32(smc);
    const int tid = threadIdx.x, w = tid >> 5, lane = tid & 31;
    const int b = blockIdx.y >> 4, h = blockIdx.y & 15;
    const int q0 = blockIdx.x * 128;
    const size_t bbase = (size_t)b * S_ * (3 * D_) + h * DH_;

    // ---- Q tiles via cp.async ----
#pragma unroll
    for (int q = 0; q < 8; ++q) {
        const int c = q * 256 + tid;               // 0..2047
        const int arr = c >> 10, rem = c & 1023;
        const int row = rem >> 3, c16 = rem & 7;
        const uint32_t dst = smb + (arr ? FQLO : FQHI) * 2 + row * (FP * 2) + c16 * 16;
        const __nv_bfloat16* src = (arr ? ql : qh) + bbase
                                   + (size_t)(q0 + row) * (3 * D_) + c16 * 8;
        CP16(dst, src);
    }

    float sacc[8][4], oacc[8][4];
    float m0v = -1e30f, m1v = -1e30f, l0v = 0.f, l1v = 0.f;
#pragma unroll
    for (int t = 0; t < 8; t++)
#pragma unroll
        for (int e = 0; e < 4; e++) oacc[t][e] = 0.f;

    const int a_row = lane & 15;
    const int a_kad = (lane >> 4) << 3;
    const int b_row = (lane & 7) + ((lane & 16) >> 1);
    const int b_kad = lane & 8;
    const int qwarp = q0 + w * 16;
    const int r0 = lane >> 2;
    const int c0l = (lane & 3) << 1;

    const int kend = q0 + 128;
    for (int k0 = 0; k0 < kend; k0 += 64) {
        __syncthreads();
        // ---- K,V tiles via cp.async ----
#pragma unroll
        for (int q = 0; q < 8; ++q) {
            const int c = q * 256 + tid;           // 0..2047
            const int tile = c >> 9, rem = c & 511;
            const int row = rem >> 3, c16 = rem & 7;
            static const int dsts[4] = {FKHI, FKLO, FVHI, FVLO};
            const uint32_t dst = smb + dsts[tile] * 2 + row * (FP * 2) + c16 * 16;
            const __nv_bfloat16* sp = (tile & 1) ? ql : qh;
            const size_t goff = bbase + ((tile >> 1) ? 2 * D_ : D_)
                                + (size_t)(k0 + row) * (3 * D_) + c16 * 8;
            CP16(dst, sp + goff);
        }
        CPCOMMIT(); CPWAIT0();
        __syncthreads();

        if (k0 > qwarp + 15) continue;

        // ---- S = Q K^T (3-term split) ----
#pragma unroll
        for (int t = 0; t < 8; t++)
#pragma unroll
            for (int e = 0; e < 4; e++) sacc[t][e] = 0.f;
#pragma unroll
        for (int kk = 0; kk < 4; ++kk) {
            uint32_t qhf[4], qlf[4];
            const uint32_t qoff = 2 * (uint32_t)((w * 16 + a_row) * FP + kk * 16 + a_kad);
            ldm_x4(qhf, smb + 2 * FQHI + qoff);
            ldm_x4(qlf, smb + 2 * FQLO + qoff);
#pragma unroll
            for (int jt = 0; jt < 4; ++jt) {
                uint32_t khf[4], klf[4];
                const uint32_t koff = 2 * (uint32_t)((jt * 16 + b_row) * FP + kk * 16 + b_kad);
                ldm_x4(khf, smb + 2 * FKHI + koff);
                ldm_x4(klf, smb + 2 * FKLO + koff);
                mma16816(sacc[jt * 2],     qhf, khf);
                mma16816(sacc[jt * 2 + 1], qhf, khf + 2);
                mma16816(sacc[jt * 2],     qhf, klf);
                mma16816(sacc[jt * 2 + 1], qhf, klf + 2);
                mma16816(sacc[jt * 2],     qlf, khf);
                mma16816(sacc[jt * 2 + 1], qlf, khf + 2);
            }
        }

        if (k0 + 63 > qwarp) {
#pragma unroll
            for (int t = 0; t < 8; t++) {
                const int kg = k0 + t * 8 + c0l;
#pragma unroll
                for (int e = 0; e < 4; e++) {
                    const int kge = kg + (e & 1);
                    const int qg = qwarp + r0 + ((e >> 1) << 3);
                    if (kge > qg) sacc[t][e] = -1e30f;
                }
            }
        }

        float mx0 = -1e30f, mx1 = -1e30f;
#pragma unroll
        for (int t = 0; t < 8; t++) {
            mx0 = fmaxf(mx0, fmaxf(sacc[t][0], sacc[t][1]));
            mx1 = fmaxf(mx1, fmaxf(sacc[t][2], sacc[t][3]));
        }
        mx0 = fmaxf(mx0, __shfl_xor_sync(~0u, mx0, 1));
        mx0 = fmaxf(mx0, __shfl_xor_sync(~0u, mx0, 2));
        mx1 = fmaxf(mx1, __shfl_xor_sync(~0u, mx1, 1));
        mx1 = fmaxf(mx1, __shfl_xor_sync(~0u, mx1, 2));
        const float mn0 = fmaxf(m0v, mx0), mn1 = fmaxf(m1v, mx1);
        const float al0 = exp2f((m0v - mn0) * SC2L);
        const float al1 = exp2f((m1v - mn1) * SC2L);
        float sum0 = 0.f, sum1 = 0.f;
        uint32_t ph[8][2], pl[8][2];
#pragma unroll
        for (int t = 0; t < 8; t++) {
            float p0 = exp2f((sacc[t][0] - mn0) * SC2L);
            float p1 = exp2f((sacc[t][1] - mn0) * SC2L);
            float p2 = exp2f((sacc[t][2] - mn1) * SC2L);
            float p3 = exp2f((sacc[t][3] - mn1) * SC2L);
            sum0 += p0 + p1; sum1 += p2 + p3;
            split2(p0, p1, ph[t][0], pl[t][0]);
            split2(p2, p3, ph[t][1], pl[t][1]);
        }
        sum0 += __shfl_xor_sync(~0u, sum0, 1);
        sum0 += __shfl_xor_sync(~0u, sum0, 2);
        sum1 += __shfl_xor_sync(~0u, sum1, 1);
        sum1 += __shfl_xor_sync(~0u, sum1, 2);
        l0v = l0v * al0 + sum0;
        l1v = l1v * al1 + sum1;
        m0v = mn0; m1v = mn1;
#pragma unroll
        for (int t = 0; t < 8; t++) {
            oacc[t][0] *= al0; oacc[t][1] *= al0;
            oacc[t][2] *= al1; oacc[t][3] *= al1;
        }

#pragma unroll
        for (int g = 0; g < 4; ++g) {
            uint32_t Ahf[4] = {ph[2 * g][0], ph[2 * g][1], ph[2 * g + 1][0], ph[2 * g + 1][1]};
            uint32_t Alf[4] = {pl[2 * g][0], pl[2 * g][1], pl[2 * g + 1][0], pl[2 * g + 1][1]};
#pragma unroll
            for (int dp = 0; dp < 4; ++dp) {
                uint32_t vhf[4], vlf[4];
                const uint32_t voff = 2 * (uint32_t)((g * 16 + (lane & 15)) * FP
                                                     + dp * 16 + ((lane >> 4) << 3));
                ldm_x4t(vhf, smb + 2 * FVHI + voff);
                ldm_x4t(vlf, smb + 2 * FVLO + voff);
                mma16816(oacc[dp * 2],     Ahf, vhf);
                mma16816(oacc[dp * 2 + 1], Ahf, vhf + 2);
                mma16816(oacc[dp * 2],     Alf, vhf);
                mma16816(oacc[dp * 2 + 1], Alf, vhf + 2);
                mma16816(oacc[dp * 2],     Ahf, vlf);
                mma16816(oacc[dp * 2 + 1], Ahf, vlf + 2);
            }
        }
    }

    // ---- write split output ----
    const float inv0 = 1.f / l0v, inv1 = 1.f / l1v;
    __nv_bfloat16* ohp = oh + (size_t)b * S_ * D_ + (size_t)h * DH_;
    __nv_bfloat16* olp = ol + (size_t)b * S_ * D_ + (size_t)h * DH_;
    const int row0 = q0 + w * 16 + r0;
#pragma unroll
    for (int t = 0; t < 8; t++) {
        const int c = t * 8 + c0l;
        uint32_t h01, l01, h23, l23;
        split2(oacc[t][0] * inv0, oacc[t][1] * inv0, h01, l01);
        split2(oacc[t][2] * inv1, oacc[t][3] * inv1, h23, l23);
        *(uint32_t*)&ohp[(size_t)row0 * D_ + c]       = h01;
        *(uint32_t*)&olp[(size_t)row0 * D_ + c]       = l01;
        *(uint32_t*)&ohp[(size_t)(row0 + 8) * D_ + c] = h23;
        *(uint32_t*)&olp[(size_t)(row0 + 8) * D_ + c] = l23;
    }
}

// ---------------- launch ----------------
extern "C" void kernel_launch(void* const* d_in, const int* in_sizes, int n_in,
                              void* d_out, int out_size)
{
    const float* x    = (const float*)d_in[0];
    const float* imp  = (const float*)d_in[1];
    const float* Wc   = (const float*)d_in[2];
    const float* Wq   = (const float*)d_in[3];
    const float* Wk   = (const float*)d_in[4];
    const float* Wv   = (const float*)d_in[5];
    const float* cn   = (const float*)d_in[6];
    const float* pool = (const float*)d_in[7];
    const float* WO   = (const float*)d_in[8];
    float* out = (float*)d_out;

    float* pLog;
    __nv_bfloat16 *pxh, *pxl, *pwh, *pwl, *psh, *psl, *phh, *phl;
    __nv_bfloat16 *peh, *pel, *pqh, *pql, *pah, *pal, *poh2, *pol2;
    cudaGetSymbolAddress((void**)&pLog, g_logits);
    cudaGetSymbolAddress((void**)&pxh, g_xhi);  cudaGetSymbolAddress((void**)&pxl, g_xlo);
    cudaGetSymbolAddress((void**)&pwh, g_whi);  cudaGetSymbolAddress((void**)&pwl, g_wlo);
    cudaGetSymbolAddress((void**)&psh, g_schi); cudaGetSymbolAddress((void**)&psl, g_sclo);
    cudaGetSymbolAddress((void**)&phh, g_hhi);  cudaGetSymbolAddress((void**)&phl, g_hlo);
    cudaGetSymbolAddress((void**)&peh, g_ehi);  cudaGetSymbolAddress((void**)&pel, g_elo);
    cudaGetSymbolAddress((void**)&pqh, g_qhi);  cudaGetSymbolAddress((void**)&pql, g_qlo);
    cudaGetSymbolAddress((void**)&pah, g_aohi); cudaGetSymbolAddress((void**)&pal, g_aolo);
    cudaGetSymbolAddress((void**)&poh2, g_wohi); cudaGetSymbolAddress((void**)&pol2, g_wolo);

    cudaFuncSetAttribute(mma_gemm_bf<0>, cudaFuncAttributeMaxDynamicSharedMemorySize, GEMM_SMEM);
    cudaFuncSetAttribute(mma_gemm_bf<1>, cudaFuncAttributeMaxDynamicSharedMemorySize, GEMM_SMEM);
    cudaFuncSetAttribute(flash_mma_bf, cudaFuncAttributeMaxDynamicSharedMemorySize, FLASH_SMEM);

    // one-time splits
    split4_kernel<<<8192, 256>>>(x, pxh, pxl, B_ * S_ * D_ / 4);
    concat_split_kernel<<<256, 256>>>(Wc, Wq, Wk, Wv);
    split4_kernel<<<1024, 256>>>(WO, poh2, pol2, D_ * D_ / 4);

    // logits = x @ Wall^T
    mma_gemm_bf<0><<<dim3(64, 2, 1), 256, GEMM_SMEM>>>(
        pxh, pxl, pwh, pwl, pLog, nullptr, nullptr, 8192, 256, 1024, 0, 0, 0);
    router_kernel<<<dim3(4, 8), 256>>>(imp);
    mix_compressT_kernel<<<dim3(256, 8), 256>>>(cn);
    // h = x @ sharedc^T  -> split bf16
    mma_gemm_bf<1><<<dim3(8, 2, 8), 256, GEMM_SMEM>>>(
        pxh, pxl, psh, psl, nullptr, phh, phl, 1024, 256, 1024,
        (long long)S_ * D_, (long long)R_ * D_, (long long)S_ * R_);
    mix_expandT_kernel<<<dim3(256, 3, 8), 256>>>(pool);
    // qkv = h @ eAll^T  -> split bf16
    mma_gemm_bf<1><<<dim3(8, 24, 8), 256, GEMM_SMEM>>>(
        phh, phl, peh, pel, nullptr, pqh, pql, 1024, 3 * D_, 256,
        (long long)S_ * R_, (long long)3 * D_ * R_, (long long)S_ * 3 * D_);
    // flash attention -> split bf16 aout
    flash_mma_bf<<<dim3(8, 128), 256, FLASH_SMEM>>>(pqh, pql, pah, pal);
    // out = aout @ W_O^T  (fp32)
    mma_gemm_bf<0><<<dim3(64, 8, 1), 256, GEMM_SMEM>>>(
        pah, pal, poh2, pol2, out, nullptr, nullptr, 8192, 1024, 1024, 0, 0, 0);
}